// round 11
// baseline (speedup 1.0000x reference)
#include <cuda_runtime.h>
#include <cuda_bf16.h>
#include <cstdint>

// ---------------------------------------------------------------------------
// Linear attention, fused per-token kernel, mma.sync bf16-split, 2 CTAs/SM.
//   n=2304, S=77, N=80, C=256, hidden=128, 8 heads x 16
// R8 core (proven 416us): serialized K->V GEMMs, one live acc set, fp32 K/V
// staging via disjoint-region overlay of the A tiles.
// R9: phase-6 collapse (kept; R9 regression attributed to DVFS clock sample).
// R10: (a) prefetch.global.L2 of the 640 scattered query lines at kernel
//      start; (b) phase-3 load balance - Ksum on threads 256..319 so it
//      overlaps KV on threads 0..255.
// ---------------------------------------------------------------------------

#define NTOK 2304
#define SEQ  77
#define NQ   80
#define HID  128

// fragment-ordered weight images: [kstep][gn][lane] -> uint4(hi01,hi89,lo01,lo89)
__device__ uint4 g_wk[16 * 16 * 32];   // K=256
__device__ uint4 g_wq[16 * 16 * 32];   // K=256
__device__ uint4 g_wv[8 * 16 * 32];    // K=128

// ---- helpers --------------------------------------------------------------
__device__ __forceinline__ uint32_t smem_u32(const void* p) {
    uint32_t a;
    asm("{ .reg .u64 t; cvta.to.shared.u64 t, %1; cvt.u32.u64 %0, t; }"
        : "=r"(a) : "l"(p));
    return a;
}
__device__ __forceinline__ void mma16816(float* d, const uint32_t* a,
                                         uint32_t b0, uint32_t b1) {
    asm volatile(
        "mma.sync.aligned.m16n8k16.row.col.f32.bf16.bf16.f32 "
        "{%0,%1,%2,%3}, {%4,%5,%6,%7}, {%8,%9}, {%0,%1,%2,%3};"
        : "+f"(d[0]), "+f"(d[1]), "+f"(d[2]), "+f"(d[3])
        : "r"(a[0]), "r"(a[1]), "r"(a[2]), "r"(a[3]), "r"(b0), "r"(b1));
}
__device__ __forceinline__ void ldsm4(uint32_t* r, uint32_t addr) {
    asm volatile("ldmatrix.sync.aligned.m8n8.x4.shared.b16 {%0,%1,%2,%3}, [%4];"
                 : "=r"(r[0]), "=r"(r[1]), "=r"(r[2]), "=r"(r[3]) : "r"(addr));
}
__device__ __forceinline__ uint32_t pack_hi(float v0, float v1) {
    uint32_t w;
    asm("cvt.rn.bf16x2.f32 %0, %1, %2;" : "=r"(w) : "f"(v1), "f"(v0));
    return w;  // lower half = v0
}
__device__ __forceinline__ float featmap(float x) {
    return x > 0.f ? x + 1.f : __expf(x);
}
__device__ __forceinline__ void prefetchL2(const void* p) {
    asm volatile("prefetch.global.L2 [%0];" :: "l"(p));
}

// fp32 rows -> bf16 hi/lo into smem A-tiles, row stride 264 elements (528 B)
template <int PAIRS>
__device__ __forceinline__ void conv_tile(const float* __restrict__ src,
                                          long rstride, int rows, char* hi_base,
                                          char* lo_base, int colbase, int tid) {
    for (int idx = tid; idx < rows * PAIRS; idx += 320) {
        int r = idx / PAIRS, j = idx % PAIRS;
        float2 v = *(const float2*)(src + (long)r * rstride + 2 * j);
        uint32_t hw = pack_hi(v.x, v.y);
        float r0 = v.x - __uint_as_float(hw << 16);
        float r1 = v.y - __uint_as_float(hw & 0xffff0000u);
        uint32_t lw = pack_hi(r0, r1);
        int off = (r * 264 + colbase + 2 * j) * 2;
        *(uint32_t*)(hi_base + off) = hw;
        *(uint32_t*)(lo_base + off) = lw;
    }
}

// MMA accumulation: warp (wm = wid>>1, wn = wid&1), depth-1 interleaved
// weight prefetch (low register pressure; TLP hides L2 with 20 warps/SM).
template <int KSTEPS>
__device__ __forceinline__ void gemm_acc(uint32_t ahi, uint32_t alo,
                                         const uint4* __restrict__ wimg,
                                         float acc[8][4], int wid, int lane) {
    const int wm = wid >> 1, wn = wid & 1;
    const int row_a = wm * 16 + (lane & 7) + ((lane >> 3) & 1) * 8;
    const uint32_t a_hi = ahi + row_a * 528 + (lane >> 4) * 16;
    const uint32_t a_lo = alo + row_a * 528 + (lane >> 4) * 16;
    const uint4* wbase = wimg + (wn * 8) * 32 + lane;

    uint4 wb[8];
#pragma unroll
    for (int nf = 0; nf < 8; nf++) wb[nf] = wbase[nf * 32];
    for (int ks = 0; ks < KSTEPS; ks++) {
        uint32_t ah[4], al[4];
        ldsm4(ah, a_hi + ks * 32);
        ldsm4(al, a_lo + ks * 32);
        const int ksn = (ks + 1 < KSTEPS) ? ks + 1 : ks;
#pragma unroll
        for (int nf = 0; nf < 8; nf++) {
            uint4 nxt = wbase[(ksn * 16 + nf) * 32];
            mma16816(acc[nf], ah, wb[nf].x, wb[nf].y);   // hi*Whi
            mma16816(acc[nf], ah, wb[nf].z, wb[nf].w);   // hi*Wlo
            mma16816(acc[nf], al, wb[nf].x, wb[nf].y);   // lo*Whi
            wb[nf] = nxt;
        }
    }
}

// split-plane fp32 epilogue: wn==0 warps -> dstA[row*132 + (c&63)],
// wn==1 warps -> dstB[row*132 + (c&63)].  (+bias, opt elu+1)
template <bool ACT>
__device__ __forceinline__ void epi_split(const float acc[8][4],
                                          const float* __restrict__ bias,
                                          float* dstA, float* dstB,
                                          int wid, int lane) {
    const int rowc = (wid >> 1) * 16 + (lane >> 2);
    const int col0 = (wid & 1) * 64 + (lane & 3) * 2;
    float* base = (wid & 1) ? dstB : dstA;
#pragma unroll
    for (int nf = 0; nf < 8; nf++) {
        int c = col0 + nf * 8;
        int c64 = c & 63;
        float b0 = __ldg(bias + c), b1 = __ldg(bias + c + 1);
        float v0 = acc[nf][0] + b0, v1 = acc[nf][1] + b1;
        float v2 = acc[nf][2] + b0, v3 = acc[nf][3] + b1;
        if (ACT) { v0 = featmap(v0); v1 = featmap(v1); v2 = featmap(v2); v3 = featmap(v3); }
        *(float2*)(base + rowc * 132 + c64) = make_float2(v0, v1);
        *(float2*)(base + (rowc + 8) * 132 + c64) = make_float2(v2, v3);
    }
}

// full-width fp32 epilogue (Q): dst row stride 132 fp32, cols 0..127
template <bool ACT>
__device__ __forceinline__ void epi_f32(const float acc[8][4],
                                        const float* __restrict__ bias,
                                        float* dst, int wid, int lane) {
    const int rowc = (wid >> 1) * 16 + (lane >> 2);
    const int col0 = (wid & 1) * 64 + (lane & 3) * 2;
#pragma unroll
    for (int nf = 0; nf < 8; nf++) {
        int c = col0 + nf * 8;
        float b0 = __ldg(bias + c), b1 = __ldg(bias + c + 1);
        float v0 = acc[nf][0] + b0, v1 = acc[nf][1] + b1;
        float v2 = acc[nf][2] + b0, v3 = acc[nf][3] + b1;
        if (ACT) { v0 = featmap(v0); v1 = featmap(v1); v2 = featmap(v2); v3 = featmap(v3); }
        *(float2*)(dst + rowc * 132 + c) = make_float2(v0, v1);
        *(float2*)(dst + (rowc + 8) * 132 + c) = make_float2(v2, v3);
    }
}

// ---------------------------------------------------------------------------
// prep: W[k][o] fp32 -> fragment-ordered bf16 hi/lo uint4 images
// ---------------------------------------------------------------------------
__global__ void kPrep(const float* __restrict__ Wq, const float* __restrict__ Wk,
                      const float* __restrict__ Wv) {
    int gid = blockIdx.x * 256 + threadIdx.x;
    if (gid >= 20480) return;
    const float* W;
    uint4* img;
    int rel;
    if (gid < 8192)       { W = Wk; img = g_wk; rel = gid; }
    else if (gid < 16384) { W = Wq; img = g_wq; rel = gid - 8192; }
    else                  { W = Wv; img = g_wv; rel = gid - 16384; }
    int lane = rel & 31, gnks = rel >> 5;          // gnks = ks*16 + gn
    int k0 = (gnks >> 4) * 16 + (lane & 3) * 2;
    int o  = ((gnks & 15) << 3) + (lane >> 2);
    float v0 = W[(long)k0 * 128 + o];
    float v1 = W[(long)(k0 + 1) * 128 + o];
    float v2 = W[(long)(k0 + 8) * 128 + o];
    float v3 = W[(long)(k0 + 9) * 128 + o];
    uint32_t h01 = pack_hi(v0, v1);
    uint32_t h89 = pack_hi(v2, v3);
    float r0 = v0 - __uint_as_float(h01 << 16);
    float r1 = v1 - __uint_as_float(h01 & 0xffff0000u);
    float r2 = v2 - __uint_as_float(h89 << 16);
    float r3 = v3 - __uint_as_float(h89 & 0xffff0000u);
    uint32_t l01 = pack_hi(r0, r1);
    uint32_t l89 = pack_hi(r2, r3);
    img[rel] = make_uint4(h01, h89, l01, l89);
}

// ---------------------------------------------------------------------------
// Fused kernel.  smem = 97,024 B, 320 threads, 2 CTAs/SM.
// Layout: R1 42,240 | R2 42,240 | kvs 8,192 | ks 512 | Zs 2,560 | red 1,280
// ---------------------------------------------------------------------------
enum { M_R1 = 0, M_R2 = 42240, M_KVS = 84480, M_KS = 92672,
       M_ZS = 93184, M_RED = 95744 };
#define M_SMEM 97024

__global__ void __launch_bounds__(320, 2)
kMain(const float* __restrict__ query, const float* __restrict__ x,
      const float* __restrict__ gdc, const float* __restrict__ bq,
      const float* __restrict__ bk, const float* __restrict__ bv,
      float* __restrict__ out) {
    extern __shared__ char sm[];
    const int n = blockIdx.x, tid = threadIdx.x;
    const int wid = tid >> 5, lane = tid & 31;
    char* R1 = sm + M_R1;
    char* R2 = sm + M_R2;
    float* R1f = (float*)R1;
    float* R2f = (float*)R2;
    float* kvs = (float*)(sm + M_KVS);
    float* ks  = (float*)(sm + M_KS);
    float* Zs  = (float*)(sm + M_ZS);
    float* red = (float*)(sm + M_RED);
    float* qq  = R1f;          // fp32 overlay after Q epilogue

    // ---- phase 0: L2-prefetch the 640 scattered query lines (1KB x 80) ----
    const int b = n / 576, rem = n - b * 576;
    const float* qbase = query + ((long)b * NQ * 576 + rem) * 256;
    {
        const char* qb = (const char*)qbase;
        int i0 = tid;                        // line index 0..639
        prefetchL2(qb + (long)(i0 >> 3) * (576L * 1024) + (i0 & 7) * 128);
        int i1 = tid + 320;
        prefetchL2(qb + (long)(i1 >> 3) * (576L * 1024) + (i1 & 7) * 128);
    }

    // ---- phase 1: convert x|g into A tiles --------------------------------
    conv_tile<64>(x + (long)n * SEQ * HID, HID, SEQ, R1, R2, 0, tid);
    conv_tile<64>(gdc + (long)n * SEQ * HID, HID, SEQ, R1, R2, 128, tid);
    for (int i = tid; i < 396; i += 320) {              // zero rows 77..79
        int r = 77 + i / 132, c2 = (i % 132) * 2;
        *(uint32_t*)(R1 + (r * 264 + c2) * 2) = 0;
        *(uint32_t*)(R2 + (r * 264 + c2) * 2) = 0;
    }
    __syncthreads();

    const uint32_t ahi = smem_u32(R1), alo = smem_u32(R2);

    // ---- phase 2a: K GEMM -> epilogue into dead g-half (bytes 256..527) ---
    {
        float acc[8][4];
#pragma unroll
        for (int i = 0; i < 8; i++)
#pragma unroll
            for (int p = 0; p < 4; p++) acc[i][p] = 0.f;
        gemm_acc<16>(ahi, alo, g_wk, acc, wid, lane);
        __syncthreads();                    // all K-GEMM A reads done
        // K cols 0..63 -> R1f[r*132+64+c64], cols 64..127 -> R2f[r*132+64+c64]
        epi_split<true>(acc, bk, R1f + 64, R2f + 64, wid, lane);
    }
    // no sync needed: V GEMM reads bytes 0..255 only (disjoint from K writes)

    // ---- phase 2b: V GEMM (reuses acc regs) -> epilogue into x-half -------
    {
        float acc[8][4];
#pragma unroll
        for (int i = 0; i < 8; i++)
#pragma unroll
            for (int p = 0; p < 4; p++) acc[i][p] = 0.f;
        gemm_acc<8>(ahi, alo, g_wv, acc, wid, lane);
        __syncthreads();                    // all V-GEMM A reads done
        // V cols 0..63 -> R1f[r*132+c64], cols 64..127 -> R2f[r*132+c64]
        epi_split<false>(acc, bv, R1f, R2f, wid, lane);
    }
    __syncthreads();

    // staged layouts (all fp32):
    //   K(t,c) = c<64 ? R1f[t*132+64+c] : R2f[t*132+c]
    //   V(t,c) = c<64 ? R1f[t*132+c]    : R2f[t*132+(c-64)]

    // ---- phase 3: KV (threads 0..255) || Ksum (threads 256..319) ----------
    if (tid < 256) {
        const int h = tid >> 5, l5 = tid & 31;
        const int d = l5 >> 1, dv0 = (l5 & 1) * 8;
        const int ck = h * 16 + d;                         // K column
        const float* kp = (ck < 64) ? (R1f + 64 + ck) : (R2f + ck);
        const int cv = h * 16 + dv0;                       // V column (8-block)
        const float* vp = (cv < 64) ? (R1f + cv) : (R2f + (cv - 64));
        float a[8] = {0, 0, 0, 0, 0, 0, 0, 0};
        for (int t = 0; t < SEQ; t++) {
            float kval = kp[t * 132];
            float4 va = *(const float4*)(vp + t * 132);
            float4 vb = *(const float4*)(vp + t * 132 + 4);
            a[0] = fmaf(kval, va.x, a[0]); a[1] = fmaf(kval, va.y, a[1]);
            a[2] = fmaf(kval, va.z, a[2]); a[3] = fmaf(kval, va.w, a[3]);
            a[4] = fmaf(kval, vb.x, a[4]); a[5] = fmaf(kval, vb.y, a[5]);
            a[6] = fmaf(kval, vb.z, a[6]); a[7] = fmaf(kval, vb.w, a[7]);
        }
        float* dst = kvs + tid * 8;
        *(float4*)dst = make_float4(a[0], a[1], a[2], a[3]);
        *(float4*)(dst + 4) = make_float4(a[4], a[5], a[6], a[7]);
    } else {
        const int t0 = (tid - 256) * 2;                    // 2 cols per thread
#pragma unroll
        for (int u = 0; u < 2; u++) {
            const int c = t0 + u;
            const float* kp = (c < 64) ? (R1f + 64 + c) : (R2f + c);
            float s = 0.f;
            for (int t = 0; t < SEQ; t++) s += kp[t * 132];
            ks[c] = s;
        }
    }
    __syncthreads();                                    // K/V staging dead

    // ---- phase 4: convert q, Q GEMM ---------------------------------------
    conv_tile<128>(qbase, 576L * 256, NQ, R1, R2, 0, tid);
    __syncthreads();
    {
        float acc[8][4];
#pragma unroll
        for (int i = 0; i < 8; i++)
#pragma unroll
            for (int p = 0; p < 4; p++) acc[i][p] = 0.f;
        gemm_acc<16>(ahi, alo, g_wq, acc, wid, lane);
        __syncthreads();
        epi_f32<true>(acc, bq, qq, wid, lane);          // Q = elu(.)+1 -> R1
    }
    __syncthreads();

    // ---- phase 5: Z[l][h] = 1/(Q.Ksum + eps) ------------------------------
    for (int e = tid; e < NQ * 8; e += 320) {
        int l = e >> 3, h = e & 7;
        float dot = 0.f;
#pragma unroll
        for (int d = 0; d < 16; d++)
            dot = fmaf(qq[l * 132 + h * 16 + d], ks[h * 16 + d], dot);
        Zs[e] = 1.0f / (dot + 1e-6f);
    }
    __syncthreads();

    // ---- phase 6a: qsum[h,d] = sum_l Z[l,h] * Q[l,h,d]  (two halves) ------
    if (tid < 256) {
        const int c = tid & 127, g = tid >> 7;
        const int h = c >> 4;
        float acc = 0.f;
        for (int l = g * 40; l < g * 40 + 40; l++)
            acc = fmaf(Zs[l * 8 + h], qq[l * 132 + c], acc);
        red[tid] = acc;
    }
    __syncthreads();

    // ---- phase 6b: out[h,dv] = (1/80) * sum_d qsum[h,d]*KV[h,d,dv] --------
    if (tid < HID) {
        const int h = tid >> 4, dv = tid & 15;
        float acc = 0.f;
#pragma unroll
        for (int d = 0; d < 16; d++) {
            float qs = red[h * 16 + d] + red[128 + h * 16 + d];
            acc = fmaf(qs, kvs[h * 256 + d * 16 + dv], acc);
        }
        out[(long)n * HID + tid] = acc * (1.0f / 80.0f);
    }
}

// ---------------------------------------------------------------------------
extern "C" void kernel_launch(void* const* d_in, const int* in_sizes, int n_in,
                              void* d_out, int out_size) {
    const float* query = (const float*)d_in[0];
    const float* x     = (const float*)d_in[1];
    const float* gdc   = (const float*)d_in[2];
    const float* Wq    = (const float*)d_in[3];
    const float* bq    = (const float*)d_in[4];
    const float* Wk    = (const float*)d_in[5];
    const float* bk    = (const float*)d_in[6];
    const float* Wv    = (const float*)d_in[7];
    const float* bv    = (const float*)d_in[8];
    float* out = (float*)d_out;

    cudaFuncSetAttribute(kMain, cudaFuncAttributeMaxDynamicSharedMemorySize, M_SMEM);

    kPrep<<<80, 256>>>(Wq, Wk, Wv);
    kMain<<<NTOK, 320, M_SMEM>>>(query, x, gdc, bq, bk, bv, out);
}

// round 12
// speedup vs baseline: 1.0050x; 1.0050x over previous
#include <cuda_runtime.h>
#include <cuda_bf16.h>
#include <cstdint>

// ---------------------------------------------------------------------------
// Linear attention, fused per-token kernel, mma.sync bf16-split, 2 CTAs/SM.
//   n=2304, S=77, N=80, C=256, hidden=128, 8 heads x 16
// EXACT R8 REVERT (proven 416.2us): serialized K->V GEMMs with ONE live
// accumulator set; fp32 K/V staging via disjoint-region overlay of the A
// tiles; original phase-5/6 epilogue. R9-R11 additions removed as part of a
// controlled re-baseline (R9/R11 regressions unattributable: neither code
// cost nor DVFS alone explains +36% with fixed MMA count).
//   K epilogue -> bytes 256..527 of each row (g-half, dead after K GEMM)
//   V epilogue -> bytes 0..255  of each row (x-half, dead after V GEMM)
// Split GEMM: A=Ahi+Alo, W=Whi+Wlo (bf16); D += Ahi*Whi + Ahi*Wlo + Alo*Whi.
// ---------------------------------------------------------------------------

#define NTOK 2304
#define SEQ  77
#define NQ   80
#define HID  128

// fragment-ordered weight images: [kstep][gn][lane] -> uint4(hi01,hi89,lo01,lo89)
__device__ uint4 g_wk[16 * 16 * 32];   // K=256
__device__ uint4 g_wq[16 * 16 * 32];   // K=256
__device__ uint4 g_wv[8 * 16 * 32];    // K=128

// ---- helpers --------------------------------------------------------------
__device__ __forceinline__ uint32_t smem_u32(const void* p) {
    uint32_t a;
    asm("{ .reg .u64 t; cvta.to.shared.u64 t, %1; cvt.u32.u64 %0, t; }"
        : "=r"(a) : "l"(p));
    return a;
}
__device__ __forceinline__ void mma16816(float* d, const uint32_t* a,
                                         uint32_t b0, uint32_t b1) {
    asm volatile(
        "mma.sync.aligned.m16n8k16.row.col.f32.bf16.bf16.f32 "
        "{%0,%1,%2,%3}, {%4,%5,%6,%7}, {%8,%9}, {%0,%1,%2,%3};"
        : "+f"(d[0]), "+f"(d[1]), "+f"(d[2]), "+f"(d[3])
        : "r"(a[0]), "r"(a[1]), "r"(a[2]), "r"(a[3]), "r"(b0), "r"(b1));
}
__device__ __forceinline__ void ldsm4(uint32_t* r, uint32_t addr) {
    asm volatile("ldmatrix.sync.aligned.m8n8.x4.shared.b16 {%0,%1,%2,%3}, [%4];"
                 : "=r"(r[0]), "=r"(r[1]), "=r"(r[2]), "=r"(r[3]) : "r"(addr));
}
__device__ __forceinline__ uint32_t pack_hi(float v0, float v1) {
    uint32_t w;
    asm("cvt.rn.bf16x2.f32 %0, %1, %2;" : "=r"(w) : "f"(v1), "f"(v0));
    return w;  // lower half = v0
}
__device__ __forceinline__ float featmap(float x) {
    return x > 0.f ? x + 1.f : __expf(x);
}

// fp32 rows -> bf16 hi/lo into smem A-tiles, row stride 264 elements (528 B)
template <int PAIRS>
__device__ __forceinline__ void conv_tile(const float* __restrict__ src,
                                          long rstride, int rows, char* hi_base,
                                          char* lo_base, int colbase, int tid) {
    for (int idx = tid; idx < rows * PAIRS; idx += 320) {
        int r = idx / PAIRS, j = idx % PAIRS;
        float2 v = *(const float2*)(src + (long)r * rstride + 2 * j);
        uint32_t hw = pack_hi(v.x, v.y);
        float r0 = v.x - __uint_as_float(hw << 16);
        float r1 = v.y - __uint_as_float(hw & 0xffff0000u);
        uint32_t lw = pack_hi(r0, r1);
        int off = (r * 264 + colbase + 2 * j) * 2;
        *(uint32_t*)(hi_base + off) = hw;
        *(uint32_t*)(lo_base + off) = lw;
    }
}

// MMA accumulation: warp (wm = wid>>1, wn = wid&1), depth-1 interleaved
// weight prefetch (low register pressure; TLP hides L2 with 20 warps/SM).
template <int KSTEPS>
__device__ __forceinline__ void gemm_acc(uint32_t ahi, uint32_t alo,
                                         const uint4* __restrict__ wimg,
                                         float acc[8][4], int wid, int lane) {
    const int wm = wid >> 1, wn = wid & 1;
    const int row_a = wm * 16 + (lane & 7) + ((lane >> 3) & 1) * 8;
    const uint32_t a_hi = ahi + row_a * 528 + (lane >> 4) * 16;
    const uint32_t a_lo = alo + row_a * 528 + (lane >> 4) * 16;
    const uint4* wbase = wimg + (wn * 8) * 32 + lane;

    uint4 wb[8];
#pragma unroll
    for (int nf = 0; nf < 8; nf++) wb[nf] = wbase[nf * 32];
    for (int ks = 0; ks < KSTEPS; ks++) {
        uint32_t ah[4], al[4];
        ldsm4(ah, a_hi + ks * 32);
        ldsm4(al, a_lo + ks * 32);
        const int ksn = (ks + 1 < KSTEPS) ? ks + 1 : ks;
#pragma unroll
        for (int nf = 0; nf < 8; nf++) {
            uint4 nxt = wbase[(ksn * 16 + nf) * 32];
            mma16816(acc[nf], ah, wb[nf].x, wb[nf].y);   // hi*Whi
            mma16816(acc[nf], ah, wb[nf].z, wb[nf].w);   // hi*Wlo
            mma16816(acc[nf], al, wb[nf].x, wb[nf].y);   // lo*Whi
            wb[nf] = nxt;
        }
    }
}

// split-plane fp32 epilogue: wn==0 warps -> dstA[row*132 + (c&63)],
// wn==1 warps -> dstB[row*132 + (c&63)].  (+bias, opt elu+1)
template <bool ACT>
__device__ __forceinline__ void epi_split(const float acc[8][4],
                                          const float* __restrict__ bias,
                                          float* dstA, float* dstB,
                                          int wid, int lane) {
    const int rowc = (wid >> 1) * 16 + (lane >> 2);
    const int col0 = (wid & 1) * 64 + (lane & 3) * 2;
    float* base = (wid & 1) ? dstB : dstA;
#pragma unroll
    for (int nf = 0; nf < 8; nf++) {
        int c = col0 + nf * 8;
        int c64 = c & 63;
        float b0 = __ldg(bias + c), b1 = __ldg(bias + c + 1);
        float v0 = acc[nf][0] + b0, v1 = acc[nf][1] + b1;
        float v2 = acc[nf][2] + b0, v3 = acc[nf][3] + b1;
        if (ACT) { v0 = featmap(v0); v1 = featmap(v1); v2 = featmap(v2); v3 = featmap(v3); }
        *(float2*)(base + rowc * 132 + c64) = make_float2(v0, v1);
        *(float2*)(base + (rowc + 8) * 132 + c64) = make_float2(v2, v3);
    }
}

// full-width fp32 epilogue (Q): dst row stride 132 fp32, cols 0..127
template <bool ACT>
__device__ __forceinline__ void epi_f32(const float acc[8][4],
                                        const float* __restrict__ bias,
                                        float* dst, int wid, int lane) {
    const int rowc = (wid >> 1) * 16 + (lane >> 2);
    const int col0 = (wid & 1) * 64 + (lane & 3) * 2;
#pragma unroll
    for (int nf = 0; nf < 8; nf++) {
        int c = col0 + nf * 8;
        float b0 = __ldg(bias + c), b1 = __ldg(bias + c + 1);
        float v0 = acc[nf][0] + b0, v1 = acc[nf][1] + b1;
        float v2 = acc[nf][2] + b0, v3 = acc[nf][3] + b1;
        if (ACT) { v0 = featmap(v0); v1 = featmap(v1); v2 = featmap(v2); v3 = featmap(v3); }
        *(float2*)(dst + rowc * 132 + c) = make_float2(v0, v1);
        *(float2*)(dst + (rowc + 8) * 132 + c) = make_float2(v2, v3);
    }
}

// ---------------------------------------------------------------------------
// prep: W[k][o] fp32 -> fragment-ordered bf16 hi/lo uint4 images
// ---------------------------------------------------------------------------
__global__ void kPrep(const float* __restrict__ Wq, const float* __restrict__ Wk,
                      const float* __restrict__ Wv) {
    int gid = blockIdx.x * 256 + threadIdx.x;
    if (gid >= 20480) return;
    const float* W;
    uint4* img;
    int rel;
    if (gid < 8192)       { W = Wk; img = g_wk; rel = gid; }
    else if (gid < 16384) { W = Wq; img = g_wq; rel = gid - 8192; }
    else                  { W = Wv; img = g_wv; rel = gid - 16384; }
    int lane = rel & 31, gnks = rel >> 5;          // gnks = ks*16 + gn
    int k0 = (gnks >> 4) * 16 + (lane & 3) * 2;
    int o  = ((gnks & 15) << 3) + (lane >> 2);
    float v0 = W[(long)k0 * 128 + o];
    float v1 = W[(long)(k0 + 1) * 128 + o];
    float v2 = W[(long)(k0 + 8) * 128 + o];
    float v3 = W[(long)(k0 + 9) * 128 + o];
    uint32_t h01 = pack_hi(v0, v1);
    uint32_t h89 = pack_hi(v2, v3);
    float r0 = v0 - __uint_as_float(h01 << 16);
    float r1 = v1 - __uint_as_float(h01 & 0xffff0000u);
    float r2 = v2 - __uint_as_float(h89 << 16);
    float r3 = v3 - __uint_as_float(h89 & 0xffff0000u);
    uint32_t l01 = pack_hi(r0, r1);
    uint32_t l89 = pack_hi(r2, r3);
    img[rel] = make_uint4(h01, h89, l01, l89);
}

// ---------------------------------------------------------------------------
// Fused kernel.  smem = 97,024 B, 320 threads, 2 CTAs/SM.
// Layout: R1 42,240 | R2 42,240 | kvs 8,192 | ks 512 | Zs 2,560 | red 1,280
// ---------------------------------------------------------------------------
enum { M_R1 = 0, M_R2 = 42240, M_KVS = 84480, M_KS = 92672,
       M_ZS = 93184, M_RED = 95744 };
#define M_SMEM 97024

__global__ void __launch_bounds__(320, 2)
kMain(const float* __restrict__ query, const float* __restrict__ x,
      const float* __restrict__ gdc, const float* __restrict__ bq,
      const float* __restrict__ bk, const float* __restrict__ bv,
      float* __restrict__ out) {
    extern __shared__ char sm[];
    const int n = blockIdx.x, tid = threadIdx.x;
    const int wid = tid >> 5, lane = tid & 31;
    char* R1 = sm + M_R1;
    char* R2 = sm + M_R2;
    float* R1f = (float*)R1;
    float* R2f = (float*)R2;
    float* kvs = (float*)(sm + M_KVS);
    float* ks  = (float*)(sm + M_KS);
    float* Zs  = (float*)(sm + M_ZS);
    float* red = (float*)(sm + M_RED);
    float* qq  = R1f;          // fp32 overlay after Q epilogue

    // ---- phase 1: convert x|g into A tiles --------------------------------
    conv_tile<64>(x + (long)n * SEQ * HID, HID, SEQ, R1, R2, 0, tid);
    conv_tile<64>(gdc + (long)n * SEQ * HID, HID, SEQ, R1, R2, 128, tid);
    for (int i = tid; i < 396; i += 320) {              // zero rows 77..79
        int r = 77 + i / 132, c2 = (i % 132) * 2;
        *(uint32_t*)(R1 + (r * 264 + c2) * 2) = 0;
        *(uint32_t*)(R2 + (r * 264 + c2) * 2) = 0;
    }
    __syncthreads();

    const uint32_t ahi = smem_u32(R1), alo = smem_u32(R2);

    // ---- phase 2a: K GEMM -> epilogue into dead g-half (bytes 256..527) ---
    {
        float acc[8][4];
#pragma unroll
        for (int i = 0; i < 8; i++)
#pragma unroll
            for (int p = 0; p < 4; p++) acc[i][p] = 0.f;
        gemm_acc<16>(ahi, alo, g_wk, acc, wid, lane);
        __syncthreads();                    // all K-GEMM A reads done
        // K cols 0..63 -> R1f[r*132+64+c64], cols 64..127 -> R2f[r*132+64+c64]
        epi_split<true>(acc, bk, R1f + 64, R2f + 64, wid, lane);
    }
    // no sync needed: V GEMM reads bytes 0..255 only (disjoint from K writes)

    // ---- phase 2b: V GEMM (reuses acc regs) -> epilogue into x-half -------
    {
        float acc[8][4];
#pragma unroll
        for (int i = 0; i < 8; i++)
#pragma unroll
            for (int p = 0; p < 4; p++) acc[i][p] = 0.f;
        gemm_acc<8>(ahi, alo, g_wv, acc, wid, lane);
        __syncthreads();                    // all V-GEMM A reads done
        // V cols 0..63 -> R1f[r*132+c64], cols 64..127 -> R2f[r*132+c64]
        epi_split<false>(acc, bv, R1f, R2f, wid, lane);
    }
    __syncthreads();

    // staged layouts (all fp32):
    //   K(t,c) = c<64 ? R1f[t*132+64+c] : R2f[t*132+c]
    //   V(t,c) = c<64 ? R1f[t*132+c]    : R2f[t*132+(c-64)]

    // ---- phase 3: Ksum + KV -----------------------------------------------
    if (tid < HID) {
        const float* kp = (tid < 64) ? (R1f + 64 + tid) : (R2f + tid);
        float s = 0.f;
        for (int t = 0; t < SEQ; t++) s += kp[t * 132];
        ks[tid] = s;
    }
    if (tid < 256) {
        const int h = tid >> 5, l5 = tid & 31;
        const int d = l5 >> 1, dv0 = (l5 & 1) * 8;
        const int ck = h * 16 + d;                         // K column
        const float* kp = (ck < 64) ? (R1f + 64 + ck) : (R2f + ck);
        const int cv = h * 16 + dv0;                       // V column (8-block)
        const float* vp = (cv < 64) ? (R1f + cv) : (R2f + (cv - 64));
        float a[8] = {0, 0, 0, 0, 0, 0, 0, 0};
        for (int t = 0; t < SEQ; t++) {
            float kval = kp[t * 132];
            float4 va = *(const float4*)(vp + t * 132);
            float4 vb = *(const float4*)(vp + t * 132 + 4);
            a[0] = fmaf(kval, va.x, a[0]); a[1] = fmaf(kval, va.y, a[1]);
            a[2] = fmaf(kval, va.z, a[2]); a[3] = fmaf(kval, va.w, a[3]);
            a[4] = fmaf(kval, vb.x, a[4]); a[5] = fmaf(kval, vb.y, a[5]);
            a[6] = fmaf(kval, vb.z, a[6]); a[7] = fmaf(kval, vb.w, a[7]);
        }
        float* dst = kvs + tid * 8;
        *(float4*)dst = make_float4(a[0], a[1], a[2], a[3]);
        *(float4*)(dst + 4) = make_float4(a[4], a[5], a[6], a[7]);
    }
    __syncthreads();                                    // K/V staging dead

    // ---- phase 4: convert q, Q GEMM ---------------------------------------
    const int b = n / 576, rem = n - b * 576;
    const float* qbase = query + ((long)b * NQ * 576 + rem) * 256;
    conv_tile<128>(qbase, 576L * 256, NQ, R1, R2, 0, tid);
    __syncthreads();
    {
        float acc[8][4];
#pragma unroll
        for (int i = 0; i < 8; i++)
#pragma unroll
            for (int p = 0; p < 4; p++) acc[i][p] = 0.f;
        gemm_acc<16>(ahi, alo, g_wq, acc, wid, lane);
        __syncthreads();
        epi_f32<true>(acc, bq, qq, wid, lane);          // Q = elu(.)+1 -> R1
    }
    __syncthreads();

    // ---- phase 5: Z[l][h] = 1/(Q.Ksum + eps) ------------------------------
    for (int e = tid; e < NQ * 8; e += 320) {
        int l = e >> 3, h = e & 7;
        float dot = 0.f;
#pragma unroll
        for (int d = 0; d < 16; d++)
            dot = fmaf(qq[l * 132 + h * 16 + d], ks[h * 16 + d], dot);
        Zs[e] = 1.0f / (dot + 1e-6f);
    }
    __syncthreads();

    // ---- phase 6: out[c] = mean_l Z[l,h] * sum_d Q[l,h,d]*KV[h,d,dv] ------
    if (tid < 256) {
        const int c = tid & 127, g = tid >> 7;
        const int h = c >> 4, dv = c & 15;
        float kvc[16];
#pragma unroll
        for (int d = 0; d < 16; d++) kvc[d] = kvs[h * 256 + d * 16 + dv];
        float acc = 0.f;
        for (int l = g * 40; l < g * 40 + 40; l++) {
            const float4* qp = (const float4*)(qq + l * 132 + h * 16);
            float4 q0 = qp[0], q1 = qp[1], q2 = qp[2], q3 = qp[3];
            float p0 = fmaf(q0.x, kvc[0],  fmaf(q0.y, kvc[1],  fmaf(q0.z, kvc[2],  q0.w * kvc[3])));
            float p1 = fmaf(q1.x, kvc[4],  fmaf(q1.y, kvc[5],  fmaf(q1.z, kvc[6],  q1.w * kvc[7])));
            float p2 = fmaf(q2.x, kvc[8],  fmaf(q2.y, kvc[9],  fmaf(q2.z, kvc[10], q2.w * kvc[11])));
            float p3 = fmaf(q3.x, kvc[12], fmaf(q3.y, kvc[13], fmaf(q3.z, kvc[14], q3.w * kvc[15])));
            acc = fmaf(Zs[l * 8 + h], (p0 + p1) + (p2 + p3), acc);
        }
        red[tid] = acc;
    }
    __syncthreads();
    if (tid < HID)
        out[(long)n * HID + tid] = (red[tid] + red[tid + HID]) * (1.0f / 80.0f);
}

// ---------------------------------------------------------------------------
extern "C" void kernel_launch(void* const* d_in, const int* in_sizes, int n_in,
                              void* d_out, int out_size) {
    const float* query = (const float*)d_in[0];
    const float* x     = (const float*)d_in[1];
    const float* gdc   = (const float*)d_in[2];
    const float* Wq    = (const float*)d_in[3];
    const float* bq    = (const float*)d_in[4];
    const float* Wk    = (const float*)d_in[5];
    const float* bk    = (const float*)d_in[6];
    const float* Wv    = (const float*)d_in[7];
    const float* bv    = (const float*)d_in[8];
    float* out = (float*)d_out;

    cudaFuncSetAttribute(kMain, cudaFuncAttributeMaxDynamicSharedMemorySize, M_SMEM);

    kPrep<<<80, 256>>>(Wq, Wk, Wv);
    kMain<<<NTOK, 320, M_SMEM>>>(query, x, gdc, bq, bk, bv, out);
}

// round 13
// speedup vs baseline: 1.3691x; 1.3623x over previous
#include <cuda_runtime.h>
#include <cuda_bf16.h>
#include <cstdint>

// ---------------------------------------------------------------------------
// Linear attention, fused per-token kernel, mma.sync bf16-split, 2 CTAs/SM.
//   n=2304, S=77, N=80, C=256, hidden=128, 8 heads x 16
// R8 core + R13: cp.async-staged weights. Each kstep's 8KB weight tile is
// staged gmem->smem ONCE per CTA (double-buffered, 1 sync/kstep), consumed
// via conflict-free LDS.128. Removes the 5x redundant per-warp weight LDG
// stream that pinned L1 at 64% and capped tensor at 39%.
//   K epilogue -> bytes 256..527 of each row (g-half, dead after K GEMM)
//   V epilogue -> bytes 0..255  of each row (x-half, dead after V GEMM)
// Split GEMM: A=Ahi+Alo, W=Whi+Wlo (bf16); D += Ahi*Whi + Ahi*Wlo + Alo*Whi.
// ---------------------------------------------------------------------------

#define NTOK 2304
#define SEQ  77
#define NQ   80
#define HID  128

// fragment-ordered weight images: [kstep][gn][lane] -> uint4(hi01,hi89,lo01,lo89)
__device__ uint4 g_wk[16 * 16 * 32];   // K=256
__device__ uint4 g_wq[16 * 16 * 32];   // K=256
__device__ uint4 g_wv[8 * 16 * 32];    // K=128

// ---- helpers --------------------------------------------------------------
__device__ __forceinline__ uint32_t smem_u32(const void* p) {
    uint32_t a;
    asm("{ .reg .u64 t; cvta.to.shared.u64 t, %1; cvt.u32.u64 %0, t; }"
        : "=r"(a) : "l"(p));
    return a;
}
__device__ __forceinline__ void mma16816(float* d, const uint32_t* a,
                                         uint32_t b0, uint32_t b1) {
    asm volatile(
        "mma.sync.aligned.m16n8k16.row.col.f32.bf16.bf16.f32 "
        "{%0,%1,%2,%3}, {%4,%5,%6,%7}, {%8,%9}, {%0,%1,%2,%3};"
        : "+f"(d[0]), "+f"(d[1]), "+f"(d[2]), "+f"(d[3])
        : "r"(a[0]), "r"(a[1]), "r"(a[2]), "r"(a[3]), "r"(b0), "r"(b1));
}
__device__ __forceinline__ void ldsm4(uint32_t* r, uint32_t addr) {
    asm volatile("ldmatrix.sync.aligned.m8n8.x4.shared.b16 {%0,%1,%2,%3}, [%4];"
                 : "=r"(r[0]), "=r"(r[1]), "=r"(r[2]), "=r"(r[3]) : "r"(addr));
}
__device__ __forceinline__ uint4 lds128(uint32_t a) {
    uint4 v;
    asm volatile("ld.shared.v4.u32 {%0,%1,%2,%3}, [%4];"
                 : "=r"(v.x), "=r"(v.y), "=r"(v.z), "=r"(v.w) : "r"(a));
    return v;
}
__device__ __forceinline__ void cp16(uint32_t dst, const void* src) {
    asm volatile("cp.async.cg.shared.global [%0], [%1], 16;"
                 :: "r"(dst), "l"(src));
}
__device__ __forceinline__ uint32_t pack_hi(float v0, float v1) {
    uint32_t w;
    asm("cvt.rn.bf16x2.f32 %0, %1, %2;" : "=r"(w) : "f"(v1), "f"(v0));
    return w;  // lower half = v0
}
__device__ __forceinline__ float featmap(float x) {
    return x > 0.f ? x + 1.f : __expf(x);
}

// fp32 rows -> bf16 hi/lo into smem A-tiles, row stride 264 elements (528 B)
template <int PAIRS>
__device__ __forceinline__ void conv_tile(const float* __restrict__ src,
                                          long rstride, int rows, char* hi_base,
                                          char* lo_base, int colbase, int tid) {
    for (int idx = tid; idx < rows * PAIRS; idx += 320) {
        int r = idx / PAIRS, j = idx % PAIRS;
        float2 v = *(const float2*)(src + (long)r * rstride + 2 * j);
        uint32_t hw = pack_hi(v.x, v.y);
        float r0 = v.x - __uint_as_float(hw << 16);
        float r1 = v.y - __uint_as_float(hw & 0xffff0000u);
        uint32_t lw = pack_hi(r0, r1);
        int off = (r * 264 + colbase + 2 * j) * 2;
        *(uint32_t*)(hi_base + off) = hw;
        *(uint32_t*)(lo_base + off) = lw;
    }
}

// MMA with cp.async-staged weights. Double-buffered 8KB stages in smem (ws),
// one __syncthreads per kstep:
//   iter ks: wait_group 0 (stage ks landed) ; sync (also: everyone done
//   reading buf (ks+1)&1 from iter ks-1) ; issue stage ks+1 into (ks+1)&1 ;
//   commit ; compute from buf ks&1 via LDS.128 (nf prefetch-by-1).
template <int KSTEPS>
__device__ __forceinline__ void gemm_cp(uint32_t ahi, uint32_t alo,
                                        const uint4* __restrict__ wimg,
                                        uint32_t ws, float acc[8][4],
                                        int wid, int lane, int tid) {
    const int wm = wid >> 1, wn = wid & 1;
    const int row_a = wm * 16 + (lane & 7) + ((lane >> 3) & 1) * 8;
    const uint32_t a_hi = ahi + row_a * 528 + (lane >> 4) * 16;
    const uint32_t a_lo = alo + row_a * 528 + (lane >> 4) * 16;

    // prologue: stage 0 -> buf 0
    if (tid < 256) {
        cp16(ws + tid * 16, wimg + tid);
        cp16(ws + tid * 16 + 4096, wimg + tid + 256);
    }
    asm volatile("cp.async.commit_group;" ::: "memory");

    for (int ks = 0; ks < KSTEPS; ks++) {
        asm volatile("cp.async.wait_group 0;" ::: "memory");
        __syncthreads();
        if (ks + 1 < KSTEPS && tid < 256) {
            const uint4* src = wimg + (ks + 1) * 512 + tid;
            uint32_t dst = ws + ((ks + 1) & 1) * 8192 + tid * 16;
            cp16(dst, src);
            cp16(dst + 4096, src + 256);
        }
        asm volatile("cp.async.commit_group;" ::: "memory");

        uint32_t ah[4], al[4];
        ldsm4(ah, a_hi + ks * 32);
        ldsm4(al, a_lo + ks * 32);
        const uint32_t wsb = ws + (ks & 1) * 8192 + wn * 4096 + lane * 16;
        uint4 w = lds128(wsb);
#pragma unroll
        for (int nf = 0; nf < 8; nf++) {
            uint4 wnx = (nf < 7) ? lds128(wsb + (nf + 1) * 512) : w;
            mma16816(acc[nf], ah, w.x, w.y);   // hi*Whi
            mma16816(acc[nf], ah, w.z, w.w);   // hi*Wlo
            mma16816(acc[nf], al, w.x, w.y);   // lo*Whi
            w = wnx;
        }
    }
}

// split-plane fp32 epilogue: wn==0 warps -> dstA[row*132 + (c&63)],
// wn==1 warps -> dstB[row*132 + (c&63)].  (+bias, opt elu+1)
template <bool ACT>
__device__ __forceinline__ void epi_split(const float acc[8][4],
                                          const float* __restrict__ bias,
                                          float* dstA, float* dstB,
                                          int wid, int lane) {
    const int rowc = (wid >> 1) * 16 + (lane >> 2);
    const int col0 = (wid & 1) * 64 + (lane & 3) * 2;
    float* base = (wid & 1) ? dstB : dstA;
#pragma unroll
    for (int nf = 0; nf < 8; nf++) {
        int c = col0 + nf * 8;
        int c64 = c & 63;
        float b0 = __ldg(bias + c), b1 = __ldg(bias + c + 1);
        float v0 = acc[nf][0] + b0, v1 = acc[nf][1] + b1;
        float v2 = acc[nf][2] + b0, v3 = acc[nf][3] + b1;
        if (ACT) { v0 = featmap(v0); v1 = featmap(v1); v2 = featmap(v2); v3 = featmap(v3); }
        *(float2*)(base + rowc * 132 + c64) = make_float2(v0, v1);
        *(float2*)(base + (rowc + 8) * 132 + c64) = make_float2(v2, v3);
    }
}

// full-width fp32 epilogue (Q): dst row stride 132 fp32, cols 0..127
template <bool ACT>
__device__ __forceinline__ void epi_f32(const float acc[8][4],
                                        const float* __restrict__ bias,
                                        float* dst, int wid, int lane) {
    const int rowc = (wid >> 1) * 16 + (lane >> 2);
    const int col0 = (wid & 1) * 64 + (lane & 3) * 2;
#pragma unroll
    for (int nf = 0; nf < 8; nf++) {
        int c = col0 + nf * 8;
        float b0 = __ldg(bias + c), b1 = __ldg(bias + c + 1);
        float v0 = acc[nf][0] + b0, v1 = acc[nf][1] + b1;
        float v2 = acc[nf][2] + b0, v3 = acc[nf][3] + b1;
        if (ACT) { v0 = featmap(v0); v1 = featmap(v1); v2 = featmap(v2); v3 = featmap(v3); }
        *(float2*)(dst + rowc * 132 + c) = make_float2(v0, v1);
        *(float2*)(dst + (rowc + 8) * 132 + c) = make_float2(v2, v3);
    }
}

// ---------------------------------------------------------------------------
// prep: W[k][o] fp32 -> fragment-ordered bf16 hi/lo uint4 images
// ---------------------------------------------------------------------------
__global__ void kPrep(const float* __restrict__ Wq, const float* __restrict__ Wk,
                      const float* __restrict__ Wv) {
    int gid = blockIdx.x * 256 + threadIdx.x;
    if (gid >= 20480) return;
    const float* W;
    uint4* img;
    int rel;
    if (gid < 8192)       { W = Wk; img = g_wk; rel = gid; }
    else if (gid < 16384) { W = Wq; img = g_wq; rel = gid - 8192; }
    else                  { W = Wv; img = g_wv; rel = gid - 16384; }
    int lane = rel & 31, gnks = rel >> 5;          // gnks = ks*16 + gn
    int k0 = (gnks >> 4) * 16 + (lane & 3) * 2;
    int o  = ((gnks & 15) << 3) + (lane >> 2);
    float v0 = W[(long)k0 * 128 + o];
    float v1 = W[(long)(k0 + 1) * 128 + o];
    float v2 = W[(long)(k0 + 8) * 128 + o];
    float v3 = W[(long)(k0 + 9) * 128 + o];
    uint32_t h01 = pack_hi(v0, v1);
    uint32_t h89 = pack_hi(v2, v3);
    float r0 = v0 - __uint_as_float(h01 << 16);
    float r1 = v1 - __uint_as_float(h01 & 0xffff0000u);
    float r2 = v2 - __uint_as_float(h89 << 16);
    float r3 = v3 - __uint_as_float(h89 & 0xffff0000u);
    uint32_t l01 = pack_hi(r0, r1);
    uint32_t l89 = pack_hi(r2, r3);
    img[rel] = make_uint4(h01, h89, l01, l89);
}

// ---------------------------------------------------------------------------
// Fused kernel.  smem = 113,408 B, 320 threads, 2 CTAs/SM.
// Layout: R1 42,240 | R2 42,240 | kvs 8,192 | ks 512 | Zs 2,560 | red 1,280
//         | WS (weight stages) 16,384
// ---------------------------------------------------------------------------
enum { M_R1 = 0, M_R2 = 42240, M_KVS = 84480, M_KS = 92672,
       M_ZS = 93184, M_RED = 95744, M_WS = 97024 };
#define M_SMEM 113408

__global__ void __launch_bounds__(320, 2)
kMain(const float* __restrict__ query, const float* __restrict__ x,
      const float* __restrict__ gdc, const float* __restrict__ bq,
      const float* __restrict__ bk, const float* __restrict__ bv,
      float* __restrict__ out) {
    extern __shared__ char sm[];
    const int n = blockIdx.x, tid = threadIdx.x;
    const int wid = tid >> 5, lane = tid & 31;
    char* R1 = sm + M_R1;
    char* R2 = sm + M_R2;
    float* R1f = (float*)R1;
    float* R2f = (float*)R2;
    float* kvs = (float*)(sm + M_KVS);
    float* ks  = (float*)(sm + M_KS);
    float* Zs  = (float*)(sm + M_ZS);
    float* red = (float*)(sm + M_RED);
    float* qq  = R1f;          // fp32 overlay after Q epilogue

    // ---- phase 1: convert x|g into A tiles --------------------------------
    conv_tile<64>(x + (long)n * SEQ * HID, HID, SEQ, R1, R2, 0, tid);
    conv_tile<64>(gdc + (long)n * SEQ * HID, HID, SEQ, R1, R2, 128, tid);
    for (int i = tid; i < 396; i += 320) {              // zero rows 77..79
        int r = 77 + i / 132, c2 = (i % 132) * 2;
        *(uint32_t*)(R1 + (r * 264 + c2) * 2) = 0;
        *(uint32_t*)(R2 + (r * 264 + c2) * 2) = 0;
    }
    __syncthreads();

    const uint32_t ahi = smem_u32(R1), alo = smem_u32(R2);
    const uint32_t ws = smem_u32(sm + M_WS);

    // ---- phase 2a: K GEMM -> epilogue into dead g-half (bytes 256..527) ---
    {
        float acc[8][4];
#pragma unroll
        for (int i = 0; i < 8; i++)
#pragma unroll
            for (int p = 0; p < 4; p++) acc[i][p] = 0.f;
        gemm_cp<16>(ahi, alo, g_wk, ws, acc, wid, lane, tid);
        __syncthreads();                    // all K-GEMM A reads done
        // K cols 0..63 -> R1f[r*132+64+c64], cols 64..127 -> R2f[r*132+64+c64]
        epi_split<true>(acc, bk, R1f + 64, R2f + 64, wid, lane);
    }
    // no sync needed: V GEMM reads bytes 0..255 only (disjoint from K writes)

    // ---- phase 2b: V GEMM (reuses acc regs) -> epilogue into x-half -------
    {
        float acc[8][4];
#pragma unroll
        for (int i = 0; i < 8; i++)
#pragma unroll
            for (int p = 0; p < 4; p++) acc[i][p] = 0.f;
        gemm_cp<8>(ahi, alo, g_wv, ws, acc, wid, lane, tid);
        __syncthreads();                    // all V-GEMM A reads done
        // V cols 0..63 -> R1f[r*132+c64], cols 64..127 -> R2f[r*132+c64]
        epi_split<false>(acc, bv, R1f, R2f, wid, lane);
    }
    __syncthreads();

    // staged layouts (all fp32):
    //   K(t,c) = c<64 ? R1f[t*132+64+c] : R2f[t*132+c]
    //   V(t,c) = c<64 ? R1f[t*132+c]    : R2f[t*132+(c-64)]

    // ---- phase 3: Ksum + KV -----------------------------------------------
    if (tid < HID) {
        const float* kp = (tid < 64) ? (R1f + 64 + tid) : (R2f + tid);
        float s = 0.f;
        for (int t = 0; t < SEQ; t++) s += kp[t * 132];
        ks[tid] = s;
    }
    if (tid < 256) {
        const int h = tid >> 5, l5 = tid & 31;
        const int d = l5 >> 1, dv0 = (l5 & 1) * 8;
        const int ck = h * 16 + d;                         // K column
        const float* kp = (ck < 64) ? (R1f + 64 + ck) : (R2f + ck);
        const int cv = h * 16 + dv0;                       // V column (8-block)
        const float* vp = (cv < 64) ? (R1f + cv) : (R2f + (cv - 64));
        float a[8] = {0, 0, 0, 0, 0, 0, 0, 0};
        for (int t = 0; t < SEQ; t++) {
            float kval = kp[t * 132];
            float4 va = *(const float4*)(vp + t * 132);
            float4 vb = *(const float4*)(vp + t * 132 + 4);
            a[0] = fmaf(kval, va.x, a[0]); a[1] = fmaf(kval, va.y, a[1]);
            a[2] = fmaf(kval, va.z, a[2]); a[3] = fmaf(kval, va.w, a[3]);
            a[4] = fmaf(kval, vb.x, a[4]); a[5] = fmaf(kval, vb.y, a[5]);
            a[6] = fmaf(kval, vb.z, a[6]); a[7] = fmaf(kval, vb.w, a[7]);
        }
        float* dst = kvs + tid * 8;
        *(float4*)dst = make_float4(a[0], a[1], a[2], a[3]);
        *(float4*)(dst + 4) = make_float4(a[4], a[5], a[6], a[7]);
    }
    __syncthreads();                                    // K/V staging dead

    // ---- phase 4: convert q, Q GEMM ---------------------------------------
    const int b = n / 576, rem = n - b * 576;
    const float* qbase = query + ((long)b * NQ * 576 + rem) * 256;
    conv_tile<128>(qbase, 576L * 256, NQ, R1, R2, 0, tid);
    __syncthreads();
    {
        float acc[8][4];
#pragma unroll
        for (int i = 0; i < 8; i++)
#pragma unroll
            for (int p = 0; p < 4; p++) acc[i][p] = 0.f;
        gemm_cp<16>(ahi, alo, g_wq, ws, acc, wid, lane, tid);
        __syncthreads();
        epi_f32<true>(acc, bq, qq, wid, lane);          // Q = elu(.)+1 -> R1
    }
    __syncthreads();

    // ---- phase 5: Z[l][h] = 1/(Q.Ksum + eps) ------------------------------
    for (int e = tid; e < NQ * 8; e += 320) {
        int l = e >> 3, h = e & 7;
        float dot = 0.f;
#pragma unroll
        for (int d = 0; d < 16; d++)
            dot = fmaf(qq[l * 132 + h * 16 + d], ks[h * 16 + d], dot);
        Zs[e] = 1.0f / (dot + 1e-6f);
    }
    __syncthreads();

    // ---- phase 6: out[c] = mean_l Z[l,h] * sum_d Q[l,h,d]*KV[h,d,dv] ------
    if (tid < 256) {
        const int c = tid & 127, g = tid >> 7;
        const int h = c >> 4, dv = c & 15;
        float kvc[16];
#pragma unroll
        for (int d = 0; d < 16; d++) kvc[d] = kvs[h * 256 + d * 16 + dv];
        float acc = 0.f;
        for (int l = g * 40; l < g * 40 + 40; l++) {
            const float4* qp = (const float4*)(qq + l * 132 + h * 16);
            float4 q0 = qp[0], q1 = qp[1], q2 = qp[2], q3 = qp[3];
            float p0 = fmaf(q0.x, kvc[0],  fmaf(q0.y, kvc[1],  fmaf(q0.z, kvc[2],  q0.w * kvc[3])));
            float p1 = fmaf(q1.x, kvc[4],  fmaf(q1.y, kvc[5],  fmaf(q1.z, kvc[6],  q1.w * kvc[7])));
            float p2 = fmaf(q2.x, kvc[8],  fmaf(q2.y, kvc[9],  fmaf(q2.z, kvc[10], q2.w * kvc[11])));
            float p3 = fmaf(q3.x, kvc[12], fmaf(q3.y, kvc[13], fmaf(q3.z, kvc[14], q3.w * kvc[15])));
            acc = fmaf(Zs[l * 8 + h], (p0 + p1) + (p2 + p3), acc);
        }
        red[tid] = acc;
    }
    __syncthreads();
    if (tid < HID)
        out[(long)n * HID + tid] = (red[tid] + red[tid + HID]) * (1.0f / 80.0f);
}

// ---------------------------------------------------------------------------
extern "C" void kernel_launch(void* const* d_in, const int* in_sizes, int n_in,
                              void* d_out, int out_size) {
    const float* query = (const float*)d_in[0];
    const float* x     = (const float*)d_in[1];
    const float* gdc   = (const float*)d_in[2];
    const float* Wq    = (const float*)d_in[3];
    const float* bq    = (const float*)d_in[4];
    const float* Wk    = (const float*)d_in[5];
    const float* bk    = (const float*)d_in[6];
    const float* Wv    = (const float*)d_in[7];
    const float* bv    = (const float*)d_in[8];
    float* out = (float*)d_out;

    cudaFuncSetAttribute(kMain, cudaFuncAttributeMaxDynamicSharedMemorySize, M_SMEM);

    kPrep<<<80, 256>>>(Wq, Wk, Wv);
    kMain<<<NTOK, 320, M_SMEM>>>(query, x, gdc, bq, bk, bv, out);
}

// round 15
// speedup vs baseline: 1.4906x; 1.0888x over previous
#include <cuda_runtime.h>
#include <cuda_bf16.h>
#include <cstdint>

// ---------------------------------------------------------------------------
// Linear attention, fused per-token kernel, mma.sync bf16-split, 2 CTAs/SM.
//   n=2304, S=77, N=80, C=256, hidden=128, 8 heads x 16
// R14 = R8 weight-LDG GEMM engine (cp.async reverted: +5% at equal clock)
//     + phase-6 collapse (qsum trick, strictly less work)
//     + phase-3 balance (Ksum on warps 8-9, overlapping KV on warps 0-7).
//   K epilogue -> bytes 256..527 of each row (g-half, dead after K GEMM)
//   V epilogue -> bytes 0..255  of each row (x-half, dead after V GEMM)
// Split GEMM: A=Ahi+Alo, W=Whi+Wlo (bf16); D += Ahi*Whi + Ahi*Wlo + Alo*Whi.
// ---------------------------------------------------------------------------

#define NTOK 2304
#define SEQ  77
#define NQ   80
#define HID  128

// fragment-ordered weight images: [kstep][gn][lane] -> uint4(hi01,hi89,lo01,lo89)
__device__ uint4 g_wk[16 * 16 * 32];   // K=256
__device__ uint4 g_wq[16 * 16 * 32];   // K=256
__device__ uint4 g_wv[8 * 16 * 32];    // K=128

// ---- helpers --------------------------------------------------------------
__device__ __forceinline__ uint32_t smem_u32(const void* p) {
    uint32_t a;
    asm("{ .reg .u64 t; cvta.to.shared.u64 t, %1; cvt.u32.u64 %0, t; }"
        : "=r"(a) : "l"(p));
    return a;
}
__device__ __forceinline__ void mma16816(float* d, const uint32_t* a,
                                         uint32_t b0, uint32_t b1) {
    asm volatile(
        "mma.sync.aligned.m16n8k16.row.col.f32.bf16.bf16.f32 "
        "{%0,%1,%2,%3}, {%4,%5,%6,%7}, {%8,%9}, {%0,%1,%2,%3};"
        : "+f"(d[0]), "+f"(d[1]), "+f"(d[2]), "+f"(d[3])
        : "r"(a[0]), "r"(a[1]), "r"(a[2]), "r"(a[3]), "r"(b0), "r"(b1));
}
__device__ __forceinline__ void ldsm4(uint32_t* r, uint32_t addr) {
    asm volatile("ldmatrix.sync.aligned.m8n8.x4.shared.b16 {%0,%1,%2,%3}, [%4];"
                 : "=r"(r[0]), "=r"(r[1]), "=r"(r[2]), "=r"(r[3]) : "r"(addr));
}
__device__ __forceinline__ uint32_t pack_hi(float v0, float v1) {
    uint32_t w;
    asm("cvt.rn.bf16x2.f32 %0, %1, %2;" : "=r"(w) : "f"(v1), "f"(v0));
    return w;  // lower half = v0
}
__device__ __forceinline__ float featmap(float x) {
    return x > 0.f ? x + 1.f : __expf(x);
}

// fp32 rows -> bf16 hi/lo into smem A-tiles, row stride 264 elements (528 B)
template <int PAIRS>
__device__ __forceinline__ void conv_tile(const float* __restrict__ src,
                                          long rstride, int rows, char* hi_base,
                                          char* lo_base, int colbase, int tid) {
    for (int idx = tid; idx < rows * PAIRS; idx += 320) {
        int r = idx / PAIRS, j = idx % PAIRS;
        float2 v = *(const float2*)(src + (long)r * rstride + 2 * j);
        uint32_t hw = pack_hi(v.x, v.y);
        float r0 = v.x - __uint_as_float(hw << 16);
        float r1 = v.y - __uint_as_float(hw & 0xffff0000u);
        uint32_t lw = pack_hi(r0, r1);
        int off = (r * 264 + colbase + 2 * j) * 2;
        *(uint32_t*)(hi_base + off) = hw;
        *(uint32_t*)(lo_base + off) = lw;
    }
}

// MMA accumulation: warp (wm = wid>>1, wn = wid&1), depth-1 interleaved
// weight prefetch (R8-proven; low register pressure, TLP hides L2).
template <int KSTEPS>
__device__ __forceinline__ void gemm_acc(uint32_t ahi, uint32_t alo,
                                         const uint4* __restrict__ wimg,
                                         float acc[8][4], int wid, int lane) {
    const int wm = wid >> 1, wn = wid & 1;
    const int row_a = wm * 16 + (lane & 7) + ((lane >> 3) & 1) * 8;
    const uint32_t a_hi = ahi + row_a * 528 + (lane >> 4) * 16;
    const uint32_t a_lo = alo + row_a * 528 + (lane >> 4) * 16;
    const uint4* wbase = wimg + (wn * 8) * 32 + lane;

    uint4 wb[8];
#pragma unroll
    for (int nf = 0; nf < 8; nf++) wb[nf] = wbase[nf * 32];
    for (int ks = 0; ks < KSTEPS; ks++) {
        uint32_t ah[4], al[4];
        ldsm4(ah, a_hi + ks * 32);
        ldsm4(al, a_lo + ks * 32);
        const int ksn = (ks + 1 < KSTEPS) ? ks + 1 : ks;
#pragma unroll
        for (int nf = 0; nf < 8; nf++) {
            uint4 nxt = wbase[(ksn * 16 + nf) * 32];
            mma16816(acc[nf], ah, wb[nf].x, wb[nf].y);   // hi*Whi
            mma16816(acc[nf], ah, wb[nf].z, wb[nf].w);   // hi*Wlo
            mma16816(acc[nf], al, wb[nf].x, wb[nf].y);   // lo*Whi
            wb[nf] = nxt;
        }
    }
}

// split-plane fp32 epilogue: wn==0 warps -> dstA[row*132 + (c&63)],
// wn==1 warps -> dstB[row*132 + (c&63)].  (+bias, opt elu+1)
template <bool ACT>
__device__ __forceinline__ void epi_split(const float acc[8][4],
                                          const float* __restrict__ bias,
                                          float* dstA, float* dstB,
                                          int wid, int lane) {
    const int rowc = (wid >> 1) * 16 + (lane >> 2);
    const int col0 = (wid & 1) * 64 + (lane & 3) * 2;
    float* base = (wid & 1) ? dstB : dstA;
#pragma unroll
    for (int nf = 0; nf < 8; nf++) {
        int c = col0 + nf * 8;
        int c64 = c & 63;
        float b0 = __ldg(bias + c), b1 = __ldg(bias + c + 1);
        float v0 = acc[nf][0] + b0, v1 = acc[nf][1] + b1;
        float v2 = acc[nf][2] + b0, v3 = acc[nf][3] + b1;
        if (ACT) { v0 = featmap(v0); v1 = featmap(v1); v2 = featmap(v2); v3 = featmap(v3); }
        *(float2*)(base + rowc * 132 + c64) = make_float2(v0, v1);
        *(float2*)(base + (rowc + 8) * 132 + c64) = make_float2(v2, v3);
    }
}

// full-width fp32 epilogue (Q): dst row stride 132 fp32, cols 0..127
template <bool ACT>
__device__ __forceinline__ void epi_f32(const float acc[8][4],
                                        const float* __restrict__ bias,
                                        float* dst, int wid, int lane) {
    const int rowc = (wid >> 1) * 16 + (lane >> 2);
    const int col0 = (wid & 1) * 64 + (lane & 3) * 2;
#pragma unroll
    for (int nf = 0; nf < 8; nf++) {
        int c = col0 + nf * 8;
        float b0 = __ldg(bias + c), b1 = __ldg(bias + c + 1);
        float v0 = acc[nf][0] + b0, v1 = acc[nf][1] + b1;
        float v2 = acc[nf][2] + b0, v3 = acc[nf][3] + b1;
        if (ACT) { v0 = featmap(v0); v1 = featmap(v1); v2 = featmap(v2); v3 = featmap(v3); }
        *(float2*)(dst + rowc * 132 + c) = make_float2(v0, v1);
        *(float2*)(dst + (rowc + 8) * 132 + c) = make_float2(v2, v3);
    }
}

// ---------------------------------------------------------------------------
// prep: W[k][o] fp32 -> fragment-ordered bf16 hi/lo uint4 images
// ---------------------------------------------------------------------------
__global__ void kPrep(const float* __restrict__ Wq, const float* __restrict__ Wk,
                      const float* __restrict__ Wv) {
    int gid = blockIdx.x * 256 + threadIdx.x;
    if (gid >= 20480) return;
    const float* W;
    uint4* img;
    int rel;
    if (gid < 8192)       { W = Wk; img = g_wk; rel = gid; }
    else if (gid < 16384) { W = Wq; img = g_wq; rel = gid - 8192; }
    else                  { W = Wv; img = g_wv; rel = gid - 16384; }
    int lane = rel & 31, gnks = rel >> 5;          // gnks = ks*16 + gn
    int k0 = (gnks >> 4) * 16 + (lane & 3) * 2;
    int o  = ((gnks & 15) << 3) + (lane >> 2);
    float v0 = W[(long)k0 * 128 + o];
    float v1 = W[(long)(k0 + 1) * 128 + o];
    float v2 = W[(long)(k0 + 8) * 128 + o];
    float v3 = W[(long)(k0 + 9) * 128 + o];
    uint32_t h01 = pack_hi(v0, v1);
    uint32_t h89 = pack_hi(v2, v3);
    float r0 = v0 - __uint_as_float(h01 << 16);
    float r1 = v1 - __uint_as_float(h01 & 0xffff0000u);
    float r2 = v2 - __uint_as_float(h89 << 16);
    float r3 = v3 - __uint_as_float(h89 & 0xffff0000u);
    uint32_t l01 = pack_hi(r0, r1);
    uint32_t l89 = pack_hi(r2, r3);
    img[rel] = make_uint4(h01, h89, l01, l89);
}

// ---------------------------------------------------------------------------
// Fused kernel.  smem = 97,024 B, 320 threads, 2 CTAs/SM.
// Layout: R1 42,240 | R2 42,240 | kvs 8,192 | ks 512 | Zs 2,560 | red 1,280
// ---------------------------------------------------------------------------
enum { M_R1 = 0, M_R2 = 42240, M_KVS = 84480, M_KS = 92672,
       M_ZS = 93184, M_RED = 95744 };
#define M_SMEM 97024

__global__ void __launch_bounds__(320, 2)
kMain(const float* __restrict__ query, const float* __restrict__ x,
      const float* __restrict__ gdc, const float* __restrict__ bq,
      const float* __restrict__ bk, const float* __restrict__ bv,
      float* __restrict__ out) {
    extern __shared__ char sm[];
    const int n = blockIdx.x, tid = threadIdx.x;
    const int wid = tid >> 5, lane = tid & 31;
    char* R1 = sm + M_R1;
    char* R2 = sm + M_R2;
    float* R1f = (float*)R1;
    float* R2f = (float*)R2;
    float* kvs = (float*)(sm + M_KVS);
    float* ks  = (float*)(sm + M_KS);
    float* Zs  = (float*)(sm + M_ZS);
    float* red = (float*)(sm + M_RED);
    float* qq  = R1f;          // fp32 overlay after Q epilogue

    // ---- phase 1: convert x|g into A tiles --------------------------------
    conv_tile<64>(x + (long)n * SEQ * HID, HID, SEQ, R1, R2, 0, tid);
    conv_tile<64>(gdc + (long)n * SEQ * HID, HID, SEQ, R1, R2, 128, tid);
    for (int i = tid; i < 396; i += 320) {              // zero rows 77..79
        int r = 77 + i / 132, c2 = (i % 132) * 2;
        *(uint32_t*)(R1 + (r * 264 + c2) * 2) = 0;
        *(uint32_t*)(R2 + (r * 264 + c2) * 2) = 0;
    }
    __syncthreads();

    const uint32_t ahi = smem_u32(R1), alo = smem_u32(R2);

    // ---- phase 2a: K GEMM -> epilogue into dead g-half (bytes 256..527) ---
    {
        float acc[8][4];
#pragma unroll
        for (int i = 0; i < 8; i++)
#pragma unroll
            for (int p = 0; p < 4; p++) acc[i][p] = 0.f;
        gemm_acc<16>(ahi, alo, g_wk, acc, wid, lane);
        __syncthreads();                    // all K-GEMM A reads done
        // K cols 0..63 -> R1f[r*132+64+c64], cols 64..127 -> R2f[r*132+64+c64]
        epi_split<true>(acc, bk, R1f + 64, R2f + 64, wid, lane);
    }
    // no sync needed: V GEMM reads bytes 0..255 only (disjoint from K writes)

    // ---- phase 2b: V GEMM (reuses acc regs) -> epilogue into x-half -------
    {
        float acc[8][4];
#pragma unroll
        for (int i = 0; i < 8; i++)
#pragma unroll
            for (int p = 0; p < 4; p++) acc[i][p] = 0.f;
        gemm_acc<8>(ahi, alo, g_wv, acc, wid, lane);
        __syncthreads();                    // all V-GEMM A reads done
        // V cols 0..63 -> R1f[r*132+c64], cols 64..127 -> R2f[r*132+c64]
        epi_split<false>(acc, bv, R1f, R2f, wid, lane);
    }
    __syncthreads();

    // staged layouts (all fp32):
    //   K(t,c) = c<64 ? R1f[t*132+64+c] : R2f[t*132+c]
    //   V(t,c) = c<64 ? R1f[t*132+c]    : R2f[t*132+(c-64)]

    // ---- phase 3: KV (threads 0..255) || Ksum (threads 256..319) ----------
    if (tid < 256) {
        const int h = tid >> 5, l5 = tid & 31;
        const int d = l5 >> 1, dv0 = (l5 & 1) * 8;
        const int ck = h * 16 + d;                         // K column
        const float* kp = (ck < 64) ? (R1f + 64 + ck) : (R2f + ck);
        const int cv = h * 16 + dv0;                       // V column (8-block)
        const float* vp = (cv < 64) ? (R1f + cv) : (R2f + (cv - 64));
        float a[8] = {0, 0, 0, 0, 0, 0, 0, 0};
        for (int t = 0; t < SEQ; t++) {
            float kval = kp[t * 132];
            float4 va = *(const float4*)(vp + t * 132);
            float4 vb = *(const float4*)(vp + t * 132 + 4);
            a[0] = fmaf(kval, va.x, a[0]); a[1] = fmaf(kval, va.y, a[1]);
            a[2] = fmaf(kval, va.z, a[2]); a[3] = fmaf(kval, va.w, a[3]);
            a[4] = fmaf(kval, vb.x, a[4]); a[5] = fmaf(kval, vb.y, a[5]);
            a[6] = fmaf(kval, vb.z, a[6]); a[7] = fmaf(kval, vb.w, a[7]);
        }
        float* dst = kvs + tid * 8;
        *(float4*)dst = make_float4(a[0], a[1], a[2], a[3]);
        *(float4*)(dst + 4) = make_float4(a[4], a[5], a[6], a[7]);
    } else {
        const int t0 = (tid - 256) * 2;                    // 2 cols per thread
#pragma unroll
        for (int u = 0; u < 2; u++) {
            const int c = t0 + u;
            const float* kp = (c < 64) ? (R1f + 64 + c) : (R2f + c);
            float s = 0.f;
            for (int t = 0; t < SEQ; t++) s += kp[t * 132];
            ks[c] = s;
        }
    }
    __syncthreads();                                    // K/V staging dead

    // ---- phase 4: convert q, Q GEMM ---------------------------------------
    const int b = n / 576, rem = n - b * 576;
    const float* qbase = query + ((long)b * NQ * 576 + rem) * 256;
    conv_tile<128>(qbase, 576L * 256, NQ, R1, R2, 0, tid);
    __syncthreads();
    {
        float acc[8][4];
#pragma unroll
        for (int i = 0; i < 8; i++)
#pragma unroll
            for (int p = 0; p < 4; p++) acc[i][p] = 0.f;
        gemm_acc<16>(ahi, alo, g_wq, acc, wid, lane);
        __syncthreads();
        epi_f32<true>(acc, bq, qq, wid, lane);          // Q = elu(.)+1 -> R1
    }
    __syncthreads();

    // ---- phase 5: Z[l][h] = 1/(Q.Ksum + eps) ------------------------------
    for (int e = tid; e < NQ * 8; e += 320) {
        int l = e >> 3, h = e & 7;
        float dot = 0.f;
#pragma unroll
        for (int d = 0; d < 16; d++)
            dot = fmaf(qq[l * 132 + h * 16 + d], ks[h * 16 + d], dot);
        Zs[e] = 1.0f / (dot + 1e-6f);
    }
    __syncthreads();

    // ---- phase 6a: qsum[h,d] = sum_l Z[l,h] * Q[l,h,d]  (two halves) ------
    if (tid < 256) {
        const int c = tid & 127, g = tid >> 7;
        const int h = c >> 4;
        float acc = 0.f;
        for (int l = g * 40; l < g * 40 + 40; l++)
            acc = fmaf(Zs[l * 8 + h], qq[l * 132 + c], acc);
        red[tid] = acc;
    }
    __syncthreads();

    // ---- phase 6b: out[h,dv] = (1/80) * sum_d qsum[h,d]*KV[h,d,dv] --------
    if (tid < HID) {
        const int h = tid >> 4, dv = tid & 15;
        float acc = 0.f;
#pragma unroll
        for (int d = 0; d < 16; d++) {
            float qs = red[h * 16 + d] + red[128 + h * 16 + d];
            acc = fmaf(qs, kvs[h * 256 + d * 16 + dv], acc);
        }
        out[(long)n * HID + tid] = acc * (1.0f / 80.0f);
    }
}

// ---------------------------------------------------------------------------
extern "C" void kernel_launch(void* const* d_in, const int* in_sizes, int n_in,
                              void* d_out, int out_size) {
    const float* query = (const float*)d_in[0];
    const float* x     = (const float*)d_in[1];
    const float* gdc   = (const float*)d_in[2];
    const float* bq    = (const float*)d_in[4];
    const float* Wq    = (const float*)d_in[3];
    const float* Wk    = (const float*)d_in[5];
    const float* bk    = (const float*)d_in[6];
    const float* Wv    = (const float*)d_in[7];
    const float* bv    = (const float*)d_in[8];
    float* out = (float*)d_out;

    cudaFuncSetAttribute(kMain, cudaFuncAttributeMaxDynamicSharedMemorySize, M_SMEM);

    kPrep<<<80, 256>>>(Wq, Wk, Wv);
    kMain<<<NTOK, 320, M_SMEM>>>(query, x, gdc, bq, bk, bv, out);
}

// round 16
// speedup vs baseline: 1.6482x; 1.1057x over previous
#include <cuda_runtime.h>
#include <cuda_bf16.h>
#include <cstdint>

// ---------------------------------------------------------------------------
// Linear attention, fused per-token kernel, mma.sync bf16-split, 2 CTAs/SM.
//   n=2304, S=77, N=80, C=256, hidden=128, 8 heads x 16
// R16 = R15 (proven 402us) + unroll of latency-chained scalar loops:
//   KV t-loop x4, Ksum t-loop x4, phase-6a l-loop x4, conv_tile x2.
// Core: R8 weight-LDG GEMM engine; serialized K->V GEMMs, one live acc set;
// fp32 K/V staging via disjoint-region overlay of the A tiles; phase-6
// collapse; phase-3 Ksum/KV overlap.
// Split GEMM: A=Ahi+Alo, W=Whi+Wlo (bf16); D += Ahi*Whi + Ahi*Wlo + Alo*Whi.
// ---------------------------------------------------------------------------

#define NTOK 2304
#define SEQ  77
#define NQ   80
#define HID  128

// fragment-ordered weight images: [kstep][gn][lane] -> uint4(hi01,hi89,lo01,lo89)
__device__ uint4 g_wk[16 * 16 * 32];   // K=256
__device__ uint4 g_wq[16 * 16 * 32];   // K=256
__device__ uint4 g_wv[8 * 16 * 32];    // K=128

// ---- helpers --------------------------------------------------------------
__device__ __forceinline__ uint32_t smem_u32(const void* p) {
    uint32_t a;
    asm("{ .reg .u64 t; cvta.to.shared.u64 t, %1; cvt.u32.u64 %0, t; }"
        : "=r"(a) : "l"(p));
    return a;
}
__device__ __forceinline__ void mma16816(float* d, const uint32_t* a,
                                         uint32_t b0, uint32_t b1) {
    asm volatile(
        "mma.sync.aligned.m16n8k16.row.col.f32.bf16.bf16.f32 "
        "{%0,%1,%2,%3}, {%4,%5,%6,%7}, {%8,%9}, {%0,%1,%2,%3};"
        : "+f"(d[0]), "+f"(d[1]), "+f"(d[2]), "+f"(d[3])
        : "r"(a[0]), "r"(a[1]), "r"(a[2]), "r"(a[3]), "r"(b0), "r"(b1));
}
__device__ __forceinline__ void ldsm4(uint32_t* r, uint32_t addr) {
    asm volatile("ldmatrix.sync.aligned.m8n8.x4.shared.b16 {%0,%1,%2,%3}, [%4];"
                 : "=r"(r[0]), "=r"(r[1]), "=r"(r[2]), "=r"(r[3]) : "r"(addr));
}
__device__ __forceinline__ uint32_t pack_hi(float v0, float v1) {
    uint32_t w;
    asm("cvt.rn.bf16x2.f32 %0, %1, %2;" : "=r"(w) : "f"(v1), "f"(v0));
    return w;  // lower half = v0
}
__device__ __forceinline__ float featmap(float x) {
    return x > 0.f ? x + 1.f : __expf(x);
}

// fp32 rows -> bf16 hi/lo into smem A-tiles, row stride 264 elements (528 B)
template <int PAIRS>
__device__ __forceinline__ void conv_tile(const float* __restrict__ src,
                                          long rstride, int rows, char* hi_base,
                                          char* lo_base, int colbase, int tid) {
#pragma unroll 2
    for (int idx = tid; idx < rows * PAIRS; idx += 320) {
        int r = idx / PAIRS, j = idx % PAIRS;
        float2 v = *(const float2*)(src + (long)r * rstride + 2 * j);
        uint32_t hw = pack_hi(v.x, v.y);
        float r0 = v.x - __uint_as_float(hw << 16);
        float r1 = v.y - __uint_as_float(hw & 0xffff0000u);
        uint32_t lw = pack_hi(r0, r1);
        int off = (r * 264 + colbase + 2 * j) * 2;
        *(uint32_t*)(hi_base + off) = hw;
        *(uint32_t*)(lo_base + off) = lw;
    }
}

// MMA accumulation: warp (wm = wid>>1, wn = wid&1), depth-1 interleaved
// weight prefetch (R8-proven; low register pressure, TLP hides L2).
template <int KSTEPS>
__device__ __forceinline__ void gemm_acc(uint32_t ahi, uint32_t alo,
                                         const uint4* __restrict__ wimg,
                                         float acc[8][4], int wid, int lane) {
    const int wm = wid >> 1, wn = wid & 1;
    const int row_a = wm * 16 + (lane & 7) + ((lane >> 3) & 1) * 8;
    const uint32_t a_hi = ahi + row_a * 528 + (lane >> 4) * 16;
    const uint32_t a_lo = alo + row_a * 528 + (lane >> 4) * 16;
    const uint4* wbase = wimg + (wn * 8) * 32 + lane;

    uint4 wb[8];
#pragma unroll
    for (int nf = 0; nf < 8; nf++) wb[nf] = wbase[nf * 32];
    for (int ks = 0; ks < KSTEPS; ks++) {
        uint32_t ah[4], al[4];
        ldsm4(ah, a_hi + ks * 32);
        ldsm4(al, a_lo + ks * 32);
        const int ksn = (ks + 1 < KSTEPS) ? ks + 1 : ks;
#pragma unroll
        for (int nf = 0; nf < 8; nf++) {
            uint4 nxt = wbase[(ksn * 16 + nf) * 32];
            mma16816(acc[nf], ah, wb[nf].x, wb[nf].y);   // hi*Whi
            mma16816(acc[nf], ah, wb[nf].z, wb[nf].w);   // hi*Wlo
            mma16816(acc[nf], al, wb[nf].x, wb[nf].y);   // lo*Whi
            wb[nf] = nxt;
        }
    }
}

// split-plane fp32 epilogue: wn==0 warps -> dstA[row*132 + (c&63)],
// wn==1 warps -> dstB[row*132 + (c&63)].  (+bias, opt elu+1)
template <bool ACT>
__device__ __forceinline__ void epi_split(const float acc[8][4],
                                          const float* __restrict__ bias,
                                          float* dstA, float* dstB,
                                          int wid, int lane) {
    const int rowc = (wid >> 1) * 16 + (lane >> 2);
    const int col0 = (wid & 1) * 64 + (lane & 3) * 2;
    float* base = (wid & 1) ? dstB : dstA;
#pragma unroll
    for (int nf = 0; nf < 8; nf++) {
        int c = col0 + nf * 8;
        int c64 = c & 63;
        float b0 = __ldg(bias + c), b1 = __ldg(bias + c + 1);
        float v0 = acc[nf][0] + b0, v1 = acc[nf][1] + b1;
        float v2 = acc[nf][2] + b0, v3 = acc[nf][3] + b1;
        if (ACT) { v0 = featmap(v0); v1 = featmap(v1); v2 = featmap(v2); v3 = featmap(v3); }
        *(float2*)(base + rowc * 132 + c64) = make_float2(v0, v1);
        *(float2*)(base + (rowc + 8) * 132 + c64) = make_float2(v2, v3);
    }
}

// full-width fp32 epilogue (Q): dst row stride 132 fp32, cols 0..127
template <bool ACT>
__device__ __forceinline__ void epi_f32(const float acc[8][4],
                                        const float* __restrict__ bias,
                                        float* dst, int wid, int lane) {
    const int rowc = (wid >> 1) * 16 + (lane >> 2);
    const int col0 = (wid & 1) * 64 + (lane & 3) * 2;
#pragma unroll
    for (int nf = 0; nf < 8; nf++) {
        int c = col0 + nf * 8;
        float b0 = __ldg(bias + c), b1 = __ldg(bias + c + 1);
        float v0 = acc[nf][0] + b0, v1 = acc[nf][1] + b1;
        float v2 = acc[nf][2] + b0, v3 = acc[nf][3] + b1;
        if (ACT) { v0 = featmap(v0); v1 = featmap(v1); v2 = featmap(v2); v3 = featmap(v3); }
        *(float2*)(dst + rowc * 132 + c) = make_float2(v0, v1);
        *(float2*)(dst + (rowc + 8) * 132 + c) = make_float2(v2, v3);
    }
}

// ---------------------------------------------------------------------------
// prep: W[k][o] fp32 -> fragment-ordered bf16 hi/lo uint4 images
// ---------------------------------------------------------------------------
__global__ void kPrep(const float* __restrict__ Wq, const float* __restrict__ Wk,
                      const float* __restrict__ Wv) {
    int gid = blockIdx.x * 256 + threadIdx.x;
    if (gid >= 20480) return;
    const float* W;
    uint4* img;
    int rel;
    if (gid < 8192)       { W = Wk; img = g_wk; rel = gid; }
    else if (gid < 16384) { W = Wq; img = g_wq; rel = gid - 8192; }
    else                  { W = Wv; img = g_wv; rel = gid - 16384; }
    int lane = rel & 31, gnks = rel >> 5;          // gnks = ks*16 + gn
    int k0 = (gnks >> 4) * 16 + (lane & 3) * 2;
    int o  = ((gnks & 15) << 3) + (lane >> 2);
    float v0 = W[(long)k0 * 128 + o];
    float v1 = W[(long)(k0 + 1) * 128 + o];
    float v2 = W[(long)(k0 + 8) * 128 + o];
    float v3 = W[(long)(k0 + 9) * 128 + o];
    uint32_t h01 = pack_hi(v0, v1);
    uint32_t h89 = pack_hi(v2, v3);
    float r0 = v0 - __uint_as_float(h01 << 16);
    float r1 = v1 - __uint_as_float(h01 & 0xffff0000u);
    float r2 = v2 - __uint_as_float(h89 << 16);
    float r3 = v3 - __uint_as_float(h89 & 0xffff0000u);
    uint32_t l01 = pack_hi(r0, r1);
    uint32_t l89 = pack_hi(r2, r3);
    img[rel] = make_uint4(h01, h89, l01, l89);
}

// ---------------------------------------------------------------------------
// Fused kernel.  smem = 97,024 B, 320 threads, 2 CTAs/SM.
// Layout: R1 42,240 | R2 42,240 | kvs 8,192 | ks 512 | Zs 2,560 | red 1,280
// ---------------------------------------------------------------------------
enum { M_R1 = 0, M_R2 = 42240, M_KVS = 84480, M_KS = 92672,
       M_ZS = 93184, M_RED = 95744 };
#define M_SMEM 97024

__global__ void __launch_bounds__(320, 2)
kMain(const float* __restrict__ query, const float* __restrict__ x,
      const float* __restrict__ gdc, const float* __restrict__ bq,
      const float* __restrict__ bk, const float* __restrict__ bv,
      float* __restrict__ out) {
    extern __shared__ char sm[];
    const int n = blockIdx.x, tid = threadIdx.x;
    const int wid = tid >> 5, lane = tid & 31;
    char* R1 = sm + M_R1;
    char* R2 = sm + M_R2;
    float* R1f = (float*)R1;
    float* R2f = (float*)R2;
    float* kvs = (float*)(sm + M_KVS);
    float* ks  = (float*)(sm + M_KS);
    float* Zs  = (float*)(sm + M_ZS);
    float* red = (float*)(sm + M_RED);
    float* qq  = R1f;          // fp32 overlay after Q epilogue

    // ---- phase 1: convert x|g into A tiles --------------------------------
    conv_tile<64>(x + (long)n * SEQ * HID, HID, SEQ, R1, R2, 0, tid);
    conv_tile<64>(gdc + (long)n * SEQ * HID, HID, SEQ, R1, R2, 128, tid);
    for (int i = tid; i < 396; i += 320) {              // zero rows 77..79
        int r = 77 + i / 132, c2 = (i % 132) * 2;
        *(uint32_t*)(R1 + (r * 264 + c2) * 2) = 0;
        *(uint32_t*)(R2 + (r * 264 + c2) * 2) = 0;
    }
    __syncthreads();

    const uint32_t ahi = smem_u32(R1), alo = smem_u32(R2);

    // ---- phase 2a: K GEMM -> epilogue into dead g-half (bytes 256..527) ---
    {
        float acc[8][4];
#pragma unroll
        for (int i = 0; i < 8; i++)
#pragma unroll
            for (int p = 0; p < 4; p++) acc[i][p] = 0.f;
        gemm_acc<16>(ahi, alo, g_wk, acc, wid, lane);
        __syncthreads();                    // all K-GEMM A reads done
        // K cols 0..63 -> R1f[r*132+64+c64], cols 64..127 -> R2f[r*132+64+c64]
        epi_split<true>(acc, bk, R1f + 64, R2f + 64, wid, lane);
    }
    // no sync needed: V GEMM reads bytes 0..255 only (disjoint from K writes)

    // ---- phase 2b: V GEMM (reuses acc regs) -> epilogue into x-half -------
    {
        float acc[8][4];
#pragma unroll
        for (int i = 0; i < 8; i++)
#pragma unroll
            for (int p = 0; p < 4; p++) acc[i][p] = 0.f;
        gemm_acc<8>(ahi, alo, g_wv, acc, wid, lane);
        __syncthreads();                    // all V-GEMM A reads done
        // V cols 0..63 -> R1f[r*132+c64], cols 64..127 -> R2f[r*132+c64]
        epi_split<false>(acc, bv, R1f, R2f, wid, lane);
    }
    __syncthreads();

    // staged layouts (all fp32):
    //   K(t,c) = c<64 ? R1f[t*132+64+c] : R2f[t*132+c]
    //   V(t,c) = c<64 ? R1f[t*132+c]    : R2f[t*132+(c-64)]

    // ---- phase 3: KV (threads 0..255) || Ksum (threads 256..319) ----------
    if (tid < 256) {
        const int h = tid >> 5, l5 = tid & 31;
        const int d = l5 >> 1, dv0 = (l5 & 1) * 8;
        const int ck = h * 16 + d;                         // K column
        const float* kp = (ck < 64) ? (R1f + 64 + ck) : (R2f + ck);
        const int cv = h * 16 + dv0;                       // V column (8-block)
        const float* vp = (cv < 64) ? (R1f + cv) : (R2f + (cv - 64));
        float a[8] = {0, 0, 0, 0, 0, 0, 0, 0};
#pragma unroll 4
        for (int t = 0; t < SEQ; t++) {
            float kval = kp[t * 132];
            float4 va = *(const float4*)(vp + t * 132);
            float4 vb = *(const float4*)(vp + t * 132 + 4);
            a[0] = fmaf(kval, va.x, a[0]); a[1] = fmaf(kval, va.y, a[1]);
            a[2] = fmaf(kval, va.z, a[2]); a[3] = fmaf(kval, va.w, a[3]);
            a[4] = fmaf(kval, vb.x, a[4]); a[5] = fmaf(kval, vb.y, a[5]);
            a[6] = fmaf(kval, vb.z, a[6]); a[7] = fmaf(kval, vb.w, a[7]);
        }
        float* dst = kvs + tid * 8;
        *(float4*)dst = make_float4(a[0], a[1], a[2], a[3]);
        *(float4*)(dst + 4) = make_float4(a[4], a[5], a[6], a[7]);
    } else {
        const int t0 = (tid - 256) * 2;                    // 2 cols per thread
#pragma unroll
        for (int u = 0; u < 2; u++) {
            const int c = t0 + u;
            const float* kp = (c < 64) ? (R1f + 64 + c) : (R2f + c);
            float s = 0.f;
#pragma unroll 4
            for (int t = 0; t < SEQ; t++) s += kp[t * 132];
            ks[c] = s;
        }
    }
    __syncthreads();                                    // K/V staging dead

    // ---- phase 4: convert q, Q GEMM ---------------------------------------
    const int b = n / 576, rem = n - b * 576;
    const float* qbase = query + ((long)b * NQ * 576 + rem) * 256;
    conv_tile<128>(qbase, 576L * 256, NQ, R1, R2, 0, tid);
    __syncthreads();
    {
        float acc[8][4];
#pragma unroll
        for (int i = 0; i < 8; i++)
#pragma unroll
            for (int p = 0; p < 4; p++) acc[i][p] = 0.f;
        gemm_acc<16>(ahi, alo, g_wq, acc, wid, lane);
        __syncthreads();
        epi_f32<true>(acc, bq, qq, wid, lane);          // Q = elu(.)+1 -> R1
    }
    __syncthreads();

    // ---- phase 5: Z[l][h] = 1/(Q.Ksum + eps) ------------------------------
    for (int e = tid; e < NQ * 8; e += 320) {
        int l = e >> 3, h = e & 7;
        float dot = 0.f;
#pragma unroll
        for (int d = 0; d < 16; d++)
            dot = fmaf(qq[l * 132 + h * 16 + d], ks[h * 16 + d], dot);
        Zs[e] = 1.0f / (dot + 1e-6f);
    }
    __syncthreads();

    // ---- phase 6a: qsum[h,d] = sum_l Z[l,h] * Q[l,h,d]  (two halves) ------
    if (tid < 256) {
        const int c = tid & 127, g = tid >> 7;
        const int h = c >> 4;
        float acc = 0.f;
#pragma unroll 4
        for (int l = g * 40; l < g * 40 + 40; l++)
            acc = fmaf(Zs[l * 8 + h], qq[l * 132 + c], acc);
        red[tid] = acc;
    }
    __syncthreads();

    // ---- phase 6b: out[h,dv] = (1/80) * sum_d qsum[h,d]*KV[h,d,dv] --------
    if (tid < HID) {
        const int h = tid >> 4, dv = tid & 15;
        float acc = 0.f;
#pragma unroll
        for (int d = 0; d < 16; d++) {
            float qs = red[h * 16 + d] + red[128 + h * 16 + d];
            acc = fmaf(qs, kvs[h * 256 + d * 16 + dv], acc);
        }
        out[(long)n * HID + tid] = acc * (1.0f / 80.0f);
    }
}

// ---------------------------------------------------------------------------
extern "C" void kernel_launch(void* const* d_in, const int* in_sizes, int n_in,
                              void* d_out, int out_size) {
    const float* query = (const float*)d_in[0];
    const float* x     = (const float*)d_in[1];
    const float* gdc   = (const float*)d_in[2];
    const float* Wq    = (const float*)d_in[3];
    const float* bq    = (const float*)d_in[4];
    const float* Wk    = (const float*)d_in[5];
    const float* bk    = (const float*)d_in[6];
    const float* Wv    = (const float*)d_in[7];
    const float* bv    = (const float*)d_in[8];
    float* out = (float*)d_out;

    cudaFuncSetAttribute(kMain, cudaFuncAttributeMaxDynamicSharedMemorySize, M_SMEM);

    kPrep<<<80, 256>>>(Wq, Wk, Wv);
    kMain<<<NTOK, 320, M_SMEM>>>(query, x, gdc, bq, bk, bv, out);
}

// round 17
// speedup vs baseline: 1.6713x; 1.0140x over previous
#include <cuda_runtime.h>
#include <cuda_bf16.h>
#include <cstdint>

// ---------------------------------------------------------------------------
// Linear attention, fused per-token kernel, mma.sync bf16-split, 2 CTAs/SM.
//   n=2304, S=77, N=80, C=256, hidden=128, 8 heads x 16
// R17 = R16 (proven 363us) + wide memory ops on serial phases:
//   conv_tile float4/uint2, phase-0 L2 prefetch of query lines,
//   phase-5 Z via float4 LDS.
// Core: R8 weight-LDG GEMM engine; serialized K->V GEMMs, one live acc set;
// fp32 K/V staging via disjoint-region overlay; phase-6 collapse; phase-3
// Ksum/KV overlap; x4 unrolled scalar reduction loops.
// Split GEMM: A=Ahi+Alo, W=Whi+Wlo (bf16); D += Ahi*Whi + Ahi*Wlo + Alo*Whi.
// ---------------------------------------------------------------------------

#define NTOK 2304
#define SEQ  77
#define NQ   80
#define HID  128

// fragment-ordered weight images: [kstep][gn][lane] -> uint4(hi01,hi89,lo01,lo89)
__device__ uint4 g_wk[16 * 16 * 32];   // K=256
__device__ uint4 g_wq[16 * 16 * 32];   // K=256
__device__ uint4 g_wv[8 * 16 * 32];    // K=128

// ---- helpers --------------------------------------------------------------
__device__ __forceinline__ uint32_t smem_u32(const void* p) {
    uint32_t a;
    asm("{ .reg .u64 t; cvta.to.shared.u64 t, %1; cvt.u32.u64 %0, t; }"
        : "=r"(a) : "l"(p));
    return a;
}
__device__ __forceinline__ void mma16816(float* d, const uint32_t* a,
                                         uint32_t b0, uint32_t b1) {
    asm volatile(
        "mma.sync.aligned.m16n8k16.row.col.f32.bf16.bf16.f32 "
        "{%0,%1,%2,%3}, {%4,%5,%6,%7}, {%8,%9}, {%0,%1,%2,%3};"
        : "+f"(d[0]), "+f"(d[1]), "+f"(d[2]), "+f"(d[3])
        : "r"(a[0]), "r"(a[1]), "r"(a[2]), "r"(a[3]), "r"(b0), "r"(b1));
}
__device__ __forceinline__ void ldsm4(uint32_t* r, uint32_t addr) {
    asm volatile("ldmatrix.sync.aligned.m8n8.x4.shared.b16 {%0,%1,%2,%3}, [%4];"
                 : "=r"(r[0]), "=r"(r[1]), "=r"(r[2]), "=r"(r[3]) : "r"(addr));
}
__device__ __forceinline__ uint32_t pack_hi(float v0, float v1) {
    uint32_t w;
    asm("cvt.rn.bf16x2.f32 %0, %1, %2;" : "=r"(w) : "f"(v1), "f"(v0));
    return w;  // lower half = v0
}
__device__ __forceinline__ float featmap(float x) {
    return x > 0.f ? x + 1.f : __expf(x);
}
__device__ __forceinline__ void prefetchL2(const void* p) {
    asm volatile("prefetch.global.L2 [%0];" :: "l"(p));
}

// fp32 rows -> bf16 hi/lo smem A-tiles, row stride 264 elems (528 B).
// float4 gmem loads, uint2 smem stores (all 8B/16B aligned).
template <int PAIRS>
__device__ __forceinline__ void conv_tile(const float* __restrict__ src,
                                          long rstride, int rows, char* hi_base,
                                          char* lo_base, int colbase, int tid) {
    const int QUADS = PAIRS / 2;
#pragma unroll 2
    for (int idx = tid; idx < rows * QUADS; idx += 320) {
        int r = idx / QUADS, j = idx % QUADS;
        float4 v = *(const float4*)(src + (long)r * rstride + 4 * j);
        uint32_t hw0 = pack_hi(v.x, v.y);
        uint32_t hw1 = pack_hi(v.z, v.w);
        float r0 = v.x - __uint_as_float(hw0 << 16);
        float r1 = v.y - __uint_as_float(hw0 & 0xffff0000u);
        float r2 = v.z - __uint_as_float(hw1 << 16);
        float r3 = v.w - __uint_as_float(hw1 & 0xffff0000u);
        uint32_t lw0 = pack_hi(r0, r1);
        uint32_t lw1 = pack_hi(r2, r3);
        int off = (r * 264 + colbase + 4 * j) * 2;
        *(uint2*)(hi_base + off) = make_uint2(hw0, hw1);
        *(uint2*)(lo_base + off) = make_uint2(lw0, lw1);
    }
}

// MMA accumulation: warp (wm = wid>>1, wn = wid&1), depth-1 interleaved
// weight prefetch (R8-proven; low register pressure, TLP hides L2).
template <int KSTEPS>
__device__ __forceinline__ void gemm_acc(uint32_t ahi, uint32_t alo,
                                         const uint4* __restrict__ wimg,
                                         float acc[8][4], int wid, int lane) {
    const int wm = wid >> 1, wn = wid & 1;
    const int row_a = wm * 16 + (lane & 7) + ((lane >> 3) & 1) * 8;
    const uint32_t a_hi = ahi + row_a * 528 + (lane >> 4) * 16;
    const uint32_t a_lo = alo + row_a * 528 + (lane >> 4) * 16;
    const uint4* wbase = wimg + (wn * 8) * 32 + lane;

    uint4 wb[8];
#pragma unroll
    for (int nf = 0; nf < 8; nf++) wb[nf] = wbase[nf * 32];
    for (int ks = 0; ks < KSTEPS; ks++) {
        uint32_t ah[4], al[4];
        ldsm4(ah, a_hi + ks * 32);
        ldsm4(al, a_lo + ks * 32);
        const int ksn = (ks + 1 < KSTEPS) ? ks + 1 : ks;
#pragma unroll
        for (int nf = 0; nf < 8; nf++) {
            uint4 nxt = wbase[(ksn * 16 + nf) * 32];
            mma16816(acc[nf], ah, wb[nf].x, wb[nf].y);   // hi*Whi
            mma16816(acc[nf], ah, wb[nf].z, wb[nf].w);   // hi*Wlo
            mma16816(acc[nf], al, wb[nf].x, wb[nf].y);   // lo*Whi
            wb[nf] = nxt;
        }
    }
}

// split-plane fp32 epilogue: wn==0 warps -> dstA[row*132 + (c&63)],
// wn==1 warps -> dstB[row*132 + (c&63)].  (+bias, opt elu+1)
template <bool ACT>
__device__ __forceinline__ void epi_split(const float acc[8][4],
                                          const float* __restrict__ bias,
                                          float* dstA, float* dstB,
                                          int wid, int lane) {
    const int rowc = (wid >> 1) * 16 + (lane >> 2);
    const int col0 = (wid & 1) * 64 + (lane & 3) * 2;
    float* base = (wid & 1) ? dstB : dstA;
#pragma unroll
    for (int nf = 0; nf < 8; nf++) {
        int c = col0 + nf * 8;
        int c64 = c & 63;
        float b0 = __ldg(bias + c), b1 = __ldg(bias + c + 1);
        float v0 = acc[nf][0] + b0, v1 = acc[nf][1] + b1;
        float v2 = acc[nf][2] + b0, v3 = acc[nf][3] + b1;
        if (ACT) { v0 = featmap(v0); v1 = featmap(v1); v2 = featmap(v2); v3 = featmap(v3); }
        *(float2*)(base + rowc * 132 + c64) = make_float2(v0, v1);
        *(float2*)(base + (rowc + 8) * 132 + c64) = make_float2(v2, v3);
    }
}

// full-width fp32 epilogue (Q): dst row stride 132 fp32, cols 0..127
template <bool ACT>
__device__ __forceinline__ void epi_f32(const float acc[8][4],
                                        const float* __restrict__ bias,
                                        float* dst, int wid, int lane) {
    const int rowc = (wid >> 1) * 16 + (lane >> 2);
    const int col0 = (wid & 1) * 64 + (lane & 3) * 2;
#pragma unroll
    for (int nf = 0; nf < 8; nf++) {
        int c = col0 + nf * 8;
        float b0 = __ldg(bias + c), b1 = __ldg(bias + c + 1);
        float v0 = acc[nf][0] + b0, v1 = acc[nf][1] + b1;
        float v2 = acc[nf][2] + b0, v3 = acc[nf][3] + b1;
        if (ACT) { v0 = featmap(v0); v1 = featmap(v1); v2 = featmap(v2); v3 = featmap(v3); }
        *(float2*)(dst + rowc * 132 + c) = make_float2(v0, v1);
        *(float2*)(dst + (rowc + 8) * 132 + c) = make_float2(v2, v3);
    }
}

// ---------------------------------------------------------------------------
// prep: W[k][o] fp32 -> fragment-ordered bf16 hi/lo uint4 images
// ---------------------------------------------------------------------------
__global__ void kPrep(const float* __restrict__ Wq, const float* __restrict__ Wk,
                      const float* __restrict__ Wv) {
    int gid = blockIdx.x * 256 + threadIdx.x;
    if (gid >= 20480) return;
    const float* W;
    uint4* img;
    int rel;
    if (gid < 8192)       { W = Wk; img = g_wk; rel = gid; }
    else if (gid < 16384) { W = Wq; img = g_wq; rel = gid - 8192; }
    else                  { W = Wv; img = g_wv; rel = gid - 16384; }
    int lane = rel & 31, gnks = rel >> 5;          // gnks = ks*16 + gn
    int k0 = (gnks >> 4) * 16 + (lane & 3) * 2;
    int o  = ((gnks & 15) << 3) + (lane >> 2);
    float v0 = W[(long)k0 * 128 + o];
    float v1 = W[(long)(k0 + 1) * 128 + o];
    float v2 = W[(long)(k0 + 8) * 128 + o];
    float v3 = W[(long)(k0 + 9) * 128 + o];
    uint32_t h01 = pack_hi(v0, v1);
    uint32_t h89 = pack_hi(v2, v3);
    float r0 = v0 - __uint_as_float(h01 << 16);
    float r1 = v1 - __uint_as_float(h01 & 0xffff0000u);
    float r2 = v2 - __uint_as_float(h89 << 16);
    float r3 = v3 - __uint_as_float(h89 & 0xffff0000u);
    uint32_t l01 = pack_hi(r0, r1);
    uint32_t l89 = pack_hi(r2, r3);
    img[rel] = make_uint4(h01, h89, l01, l89);
}

// ---------------------------------------------------------------------------
// Fused kernel.  smem = 97,024 B, 320 threads, 2 CTAs/SM.
// Layout: R1 42,240 | R2 42,240 | kvs 8,192 | ks 512 | Zs 2,560 | red 1,280
// ---------------------------------------------------------------------------
enum { M_R1 = 0, M_R2 = 42240, M_KVS = 84480, M_KS = 92672,
       M_ZS = 93184, M_RED = 95744 };
#define M_SMEM 97024

__global__ void __launch_bounds__(320, 2)
kMain(const float* __restrict__ query, const float* __restrict__ x,
      const float* __restrict__ gdc, const float* __restrict__ bq,
      const float* __restrict__ bk, const float* __restrict__ bv,
      float* __restrict__ out) {
    extern __shared__ char sm[];
    const int n = blockIdx.x, tid = threadIdx.x;
    const int wid = tid >> 5, lane = tid & 31;
    char* R1 = sm + M_R1;
    char* R2 = sm + M_R2;
    float* R1f = (float*)R1;
    float* R2f = (float*)R2;
    float* kvs = (float*)(sm + M_KVS);
    float* ks  = (float*)(sm + M_KS);
    float* Zs  = (float*)(sm + M_ZS);
    float* red = (float*)(sm + M_RED);
    float* qq  = R1f;          // fp32 overlay after Q epilogue

    // ---- phase 0: L2-prefetch the 640 scattered query lines (1KB x 80) ----
    const int b = n / 576, rem = n - b * 576;
    const float* qbase = query + ((long)b * NQ * 576 + rem) * 256;
    {
        const char* qb = (const char*)qbase;
        int i0 = tid;                        // line index 0..639
        prefetchL2(qb + (long)(i0 >> 3) * (576L * 1024) + (i0 & 7) * 128);
        int i1 = tid + 320;
        prefetchL2(qb + (long)(i1 >> 3) * (576L * 1024) + (i1 & 7) * 128);
    }

    // ---- phase 1: convert x|g into A tiles --------------------------------
    conv_tile<64>(x + (long)n * SEQ * HID, HID, SEQ, R1, R2, 0, tid);
    conv_tile<64>(gdc + (long)n * SEQ * HID, HID, SEQ, R1, R2, 128, tid);
    for (int i = tid; i < 396; i += 320) {              // zero rows 77..79
        int r = 77 + i / 132, c2 = (i % 132) * 2;
        *(uint32_t*)(R1 + (r * 264 + c2) * 2) = 0;
        *(uint32_t*)(R2 + (r * 264 + c2) * 2) = 0;
    }
    __syncthreads();

    const uint32_t ahi = smem_u32(R1), alo = smem_u32(R2);

    // ---- phase 2a: K GEMM -> epilogue into dead g-half (bytes 256..527) ---
    {
        float acc[8][4];
#pragma unroll
        for (int i = 0; i < 8; i++)
#pragma unroll
            for (int p = 0; p < 4; p++) acc[i][p] = 0.f;
        gemm_acc<16>(ahi, alo, g_wk, acc, wid, lane);
        __syncthreads();                    // all K-GEMM A reads done
        // K cols 0..63 -> R1f[r*132+64+c64], cols 64..127 -> R2f[r*132+64+c64]
        epi_split<true>(acc, bk, R1f + 64, R2f + 64, wid, lane);
    }
    // no sync needed: V GEMM reads bytes 0..255 only (disjoint from K writes)

    // ---- phase 2b: V GEMM (reuses acc regs) -> epilogue into x-half -------
    {
        float acc[8][4];
#pragma unroll
        for (int i = 0; i < 8; i++)
#pragma unroll
            for (int p = 0; p < 4; p++) acc[i][p] = 0.f;
        gemm_acc<8>(ahi, alo, g_wv, acc, wid, lane);
        __syncthreads();                    // all V-GEMM A reads done
        // V cols 0..63 -> R1f[r*132+c64], cols 64..127 -> R2f[r*132+c64]
        epi_split<false>(acc, bv, R1f, R2f, wid, lane);
    }
    __syncthreads();

    // staged layouts (all fp32):
    //   K(t,c) = c<64 ? R1f[t*132+64+c] : R2f[t*132+c]
    //   V(t,c) = c<64 ? R1f[t*132+c]    : R2f[t*132+(c-64)]

    // ---- phase 3: KV (threads 0..255) || Ksum (threads 256..319) ----------
    if (tid < 256) {
        const int h = tid >> 5, l5 = tid & 31;
        const int d = l5 >> 1, dv0 = (l5 & 1) * 8;
        const int ck = h * 16 + d;                         // K column
        const float* kp = (ck < 64) ? (R1f + 64 + ck) : (R2f + ck);
        const int cv = h * 16 + dv0;                       // V column (8-block)
        const float* vp = (cv < 64) ? (R1f + cv) : (R2f + (cv - 64));
        float a[8] = {0, 0, 0, 0, 0, 0, 0, 0};
#pragma unroll 4
        for (int t = 0; t < SEQ; t++) {
            float kval = kp[t * 132];
            float4 va = *(const float4*)(vp + t * 132);
            float4 vb = *(const float4*)(vp + t * 132 + 4);
            a[0] = fmaf(kval, va.x, a[0]); a[1] = fmaf(kval, va.y, a[1]);
            a[2] = fmaf(kval, va.z, a[2]); a[3] = fmaf(kval, va.w, a[3]);
            a[4] = fmaf(kval, vb.x, a[4]); a[5] = fmaf(kval, vb.y, a[5]);
            a[6] = fmaf(kval, vb.z, a[6]); a[7] = fmaf(kval, vb.w, a[7]);
        }
        float* dst = kvs + tid * 8;
        *(float4*)dst = make_float4(a[0], a[1], a[2], a[3]);
        *(float4*)(dst + 4) = make_float4(a[4], a[5], a[6], a[7]);
    } else {
        const int t0 = (tid - 256) * 2;                    // 2 cols per thread
#pragma unroll
        for (int u = 0; u < 2; u++) {
            const int c = t0 + u;
            const float* kp = (c < 64) ? (R1f + 64 + c) : (R2f + c);
            float s = 0.f;
#pragma unroll 4
            for (int t = 0; t < SEQ; t++) s += kp[t * 132];
            ks[c] = s;
        }
    }
    __syncthreads();                                    // K/V staging dead

    // ---- phase 4: convert q, Q GEMM ---------------------------------------
    conv_tile<128>(qbase, 576L * 256, NQ, R1, R2, 0, tid);
    __syncthreads();
    {
        float acc[8][4];
#pragma unroll
        for (int i = 0; i < 8; i++)
#pragma unroll
            for (int p = 0; p < 4; p++) acc[i][p] = 0.f;
        gemm_acc<16>(ahi, alo, g_wq, acc, wid, lane);
        __syncthreads();
        epi_f32<true>(acc, bq, qq, wid, lane);          // Q = elu(.)+1 -> R1
    }
    __syncthreads();

    // ---- phase 5: Z[l][h] = 1/(Q.Ksum + eps)  (float4 LDS) ----------------
    for (int e = tid; e < NQ * 8; e += 320) {
        int l = e >> 3, h = e & 7;
        const float4* qp = (const float4*)(qq + l * 132 + h * 16);
        const float4* kp = (const float4*)(ks + h * 16);
        float4 q0 = qp[0], q1 = qp[1], q2 = qp[2], q3 = qp[3];
        float4 k0 = kp[0], k1 = kp[1], k2 = kp[2], k3 = kp[3];
        float d0 = fmaf(q0.x, k0.x, fmaf(q0.y, k0.y, fmaf(q0.z, k0.z, q0.w * k0.w)));
        float d1 = fmaf(q1.x, k1.x, fmaf(q1.y, k1.y, fmaf(q1.z, k1.z, q1.w * k1.w)));
        float d2 = fmaf(q2.x, k2.x, fmaf(q2.y, k2.y, fmaf(q2.z, k2.z, q2.w * k2.w)));
        float d3 = fmaf(q3.x, k3.x, fmaf(q3.y, k3.y, fmaf(q3.z, k3.z, q3.w * k3.w)));
        Zs[e] = 1.0f / (((d0 + d1) + (d2 + d3)) + 1e-6f);
    }
    __syncthreads();

    // ---- phase 6a: qsum[h,d] = sum_l Z[l,h] * Q[l,h,d]  (two halves) ------
    if (tid < 256) {
        const int c = tid & 127, g = tid >> 7;
        const int h = c >> 4;
        float acc = 0.f;
#pragma unroll 4
        for (int l = g * 40; l < g * 40 + 40; l++)
            acc = fmaf(Zs[l * 8 + h], qq[l * 132 + c], acc);
        red[tid] = acc;
    }
    __syncthreads();

    // ---- phase 6b: out[h,dv] = (1/80) * sum_d qsum[h,d]*KV[h,d,dv] --------
    if (tid < HID) {
        const int h = tid >> 4, dv = tid & 15;
        float acc = 0.f;
#pragma unroll
        for (int d = 0; d < 16; d++) {
            float qs = red[h * 16 + d] + red[128 + h * 16 + d];
            acc = fmaf(qs, kvs[h * 256 + d * 16 + dv], acc);
        }
        out[(long)n * HID + tid] = acc * (1.0f / 80.0f);
    }
}

// ---------------------------------------------------------------------------
extern "C" void kernel_launch(void* const* d_in, const int* in_sizes, int n_in,
                              void* d_out, int out_size) {
    const float* query = (const float*)d_in[0];
    const float* x     = (const float*)d_in[1];
    const float* gdc   = (const float*)d_in[2];
    const float* Wq    = (const float*)d_in[3];
    const float* bq    = (const float*)d_in[4];
    const float* Wk    = (const float*)d_in[5];
    const float* bk    = (const float*)d_in[6];
    const float* Wv    = (const float*)d_in[7];
    const float* bv    = (const float*)d_in[8];
    float* out = (float*)d_out;

    cudaFuncSetAttribute(kMain, cudaFuncAttributeMaxDynamicSharedMemorySize, M_SMEM);

    kPrep<<<80, 256>>>(Wq, Wk, Wv);
    kMain<<<NTOK, 320, M_SMEM>>>(query, x, gdc, bq, bk, bv, out);
}